// round 5
// baseline (speedup 1.0000x reference)
#include <cuda_runtime.h>
#include <math.h>

// Problem constants
#define Bq 2
#define Nq 1024
#define Cc 256
#define NH 8
#define DH 32
#define FF 2048
#define HW0 35200   // 200x176
#define HW2 140800  // 400x352

// value buffer offsets (in floats), layout per level: [B, HW, 256]
#define VOFF0 0L
#define VOFF1 (2L*35200*256)
#define VOFF2 (2L*(35200+35200)*256)
#define VTOT  (2L*(35200+35200+140800)*256)

// ---------------- scratch (static device globals; no allocation) ----------------
__device__ float g_qkv[Bq*Nq*3*Cc];
__device__ float g_scores[(long)Bq*NH*Nq*Nq];   // 64 MB
__device__ float g_sa[Bq*Nq*Cc];
__device__ float g_tmp[Bq*Nq*Cc];
__device__ float g_q1[Bq*Nq*Cc];
__device__ float g_q2[Bq*Nq*Cc];
__device__ float g_off[Bq*Nq*192];
__device__ float g_aw[Bq*Nq*96];
__device__ float g_ca[Bq*Nq*Cc];
__device__ float g_ffh[Bq*Nq*FF];
__device__ float g_values[VTOT];                // 432 MB

// ---------------- f32x2 packed FMA (sm_103a full-rate fp32 path) ----------------
union F2 { float2 f; unsigned long long u; };

__device__ __forceinline__ void ffma2(F2& d, const F2& a, const F2& b) {
    asm("fma.rn.f32x2 %0, %1, %2, %0;" : "+l"(d.u) : "l"(a.u), "l"(b.u));
}

#define TM 128
#define TN 128
#define TK 16
#define SROW 132   // padded row (multiple of 4 for float4 smem ops)

__device__ __forceinline__ void mm_inner(const float (&As)[TK][SROW],
                                         const float (&Bs)[TK][SROW],
                                         F2 (&acc)[4][8], int tx, int ty)
{
    #pragma unroll
    for (int kk = 0; kk < TK; kk++) {
        float4 a0 = *(const float4*)&As[kk][ty*8];
        float4 a1 = *(const float4*)&As[kk][ty*8+4];
        float4 b0 = *(const float4*)&Bs[kk][tx*8];
        float4 b1 = *(const float4*)&Bs[kk][tx*8+4];
        F2 a2[4];
        a2[0].f = make_float2(a0.x, a0.y);
        a2[1].f = make_float2(a0.z, a0.w);
        a2[2].f = make_float2(a1.x, a1.y);
        a2[3].f = make_float2(a1.z, a1.w);
        float bv[8] = {b0.x,b0.y,b0.z,b0.w,b1.x,b1.y,b1.z,b1.w};
        #pragma unroll
        for (int j = 0; j < 8; j++) {
            F2 bd; bd.f = make_float2(bv[j], bv[j]);
            #pragma unroll
            for (int i = 0; i < 4; i++) ffma2(acc[i][j], a2[i], bd);
        }
    }
}

// Out[m,n] = sum_k A[k*M+m] * W[n*K+k] + bias[n].  A stored K-major ("transposed" A).
__global__ __launch_bounds__(256, 2)
void gemm_at_kernel(const float* __restrict__ A, const float* __restrict__ W,
                    const float* __restrict__ bias, float* __restrict__ Out,
                    int M, int Nc, int K, long sA, long sO)
{
    __shared__ float As[TK][SROW];
    __shared__ float Bs[TK][SROW];
    const float* Ab = A + (long)blockIdx.z * sA;
    float* Ob = Out + (long)blockIdx.z * sO;
    int m0 = blockIdx.x * TM, n0 = blockIdx.y * TN;
    int tid = threadIdx.x;
    int tx = tid & 15, ty = tid >> 4;
    int a_c4 = (tid & 31) * 4, a_r = tid >> 5;
    int b_j = tid >> 1, b_k = (tid & 1) * 8;
    int jglob = n0 + b_j;

    F2 acc[4][8];
    #pragma unroll
    for (int i=0;i<4;i++)
        #pragma unroll
        for (int j=0;j<8;j++) { acc[i][j].f.x = 0.f; acc[i][j].f.y = 0.f; }

    for (int k0 = 0; k0 < K; k0 += TK) {
        #pragma unroll
        for (int r = 0; r < 2; r++) {
            int kk = a_r + r*8;
            float4 v = *(const float4*)(Ab + (long)(k0+kk)*M + m0 + a_c4);
            *(float4*)&As[kk][a_c4] = v;
        }
        if (jglob < Nc) {
            const float* src = W + (long)jglob*K + k0 + b_k;
            #pragma unroll
            for (int t=0;t<8;t++) Bs[b_k+t][b_j] = src[t];
        } else {
            #pragma unroll
            for (int t=0;t<8;t++) Bs[b_k+t][b_j] = 0.f;
        }
        __syncthreads();
        mm_inner(As, Bs, acc, tx, ty);
        __syncthreads();
    }
    #pragma unroll
    for (int i=0;i<4;i++) {
        int m = m0 + ty*8 + 2*i;
        #pragma unroll
        for (int j=0;j<8;j++) {
            int n = n0 + tx*8 + j;
            if (n < Nc) {
                float bb = bias[n];
                Ob[(long)m*Nc + n]     = acc[i][j].f.x + bb;
                Ob[(long)(m+1)*Nc + n] = acc[i][j].f.y + bb;
            }
        }
    }
}

// Out[m,n] = sum_k A[m*K+k] * W[n*K+k] + bias[n], optional ReLU. A row-major.
__global__ __launch_bounds__(256, 2)
void gemm_a_kernel(const float* __restrict__ A, const float* __restrict__ W,
                   const float* __restrict__ bias, float* __restrict__ Out,
                   int M, int Nc, int K, int relu)
{
    __shared__ float As[TK][SROW];
    __shared__ float Bs[TK][SROW];
    int m0 = blockIdx.x * TM, n0 = blockIdx.y * TN;
    int tid = threadIdx.x;
    int tx = tid & 15, ty = tid >> 4;
    int a_m = tid >> 1, a_k = (tid & 1) * 8;
    int b_j = tid >> 1, b_k = (tid & 1) * 8;
    int jglob = n0 + b_j;

    F2 acc[4][8];
    #pragma unroll
    for (int i=0;i<4;i++)
        #pragma unroll
        for (int j=0;j<8;j++) { acc[i][j].f.x = 0.f; acc[i][j].f.y = 0.f; }

    for (int k0 = 0; k0 < K; k0 += TK) {
        {
            const float* src = A + (long)(m0 + a_m)*K + k0 + a_k;
            #pragma unroll
            for (int t=0;t<8;t++) As[a_k+t][a_m] = src[t];
        }
        if (jglob < Nc) {
            const float* src = W + (long)jglob*K + k0 + b_k;
            #pragma unroll
            for (int t=0;t<8;t++) Bs[b_k+t][b_j] = src[t];
        } else {
            #pragma unroll
            for (int t=0;t<8;t++) Bs[b_k+t][b_j] = 0.f;
        }
        __syncthreads();
        mm_inner(As, Bs, acc, tx, ty);
        __syncthreads();
    }
    #pragma unroll
    for (int i=0;i<4;i++) {
        int m = m0 + ty*8 + 2*i;
        #pragma unroll
        for (int j=0;j<8;j++) {
            int n = n0 + tx*8 + j;
            if (n < Nc) {
                float bb = bias[n];
                float v0 = acc[i][j].f.x + bb;
                float v1 = acc[i][j].f.y + bb;
                if (relu) { v0 = fmaxf(v0, 0.f); v1 = fmaxf(v1, 0.f); }
                Out[(long)m*Nc + n]     = v0;
                Out[(long)(m+1)*Nc + n] = v1;
            }
        }
    }
}

// ---------------- attention: scores, softmax, P@V ----------------
__global__ void scores_kernel(const float* __restrict__ qkv, float* __restrict__ scores)
{
    __shared__ float Qs[64][33];
    __shared__ float Ks[64][33];
    int bh = blockIdx.z, b = bh >> 3, h = bh & 7;
    int i0 = blockIdx.x * 64, j0 = blockIdx.y * 64;
    int tid = threadIdx.x;
    int lr = tid >> 2, ld = (tid & 3) * 8;
    {
        const float* qsrc = qkv + (long)(b*Nq + i0 + lr)*768 + h*32 + ld;
        const float* ksrc = qkv + (long)(b*Nq + j0 + lr)*768 + 256 + h*32 + ld;
        #pragma unroll
        for (int t=0;t<8;t++) { Qs[lr][ld+t] = qsrc[t]; Ks[lr][ld+t] = ksrc[t]; }
    }
    __syncthreads();
    int tx = tid & 15, ty = tid >> 4;
    float acc[4][4] = {};
    #pragma unroll
    for (int d = 0; d < 32; d++) {
        float a[4], bb[4];
        #pragma unroll
        for (int i=0;i<4;i++) a[i] = Qs[ty*4+i][d];
        #pragma unroll
        for (int j=0;j<4;j++) bb[j] = Ks[tx*4+j][d];
        #pragma unroll
        for (int i=0;i<4;i++)
            #pragma unroll
            for (int j=0;j<4;j++) acc[i][j] += a[i]*bb[j];
    }
    const float sc = 0.17677669529663689f; // 1/sqrt(32)
    #pragma unroll
    for (int i=0;i<4;i++)
        #pragma unroll
        for (int j=0;j<4;j++)
            scores[((long)bh*Nq + i0 + ty*4 + i)*Nq + j0 + tx*4 + j] = acc[i][j]*sc;
}

__global__ void softmax_kernel(float* __restrict__ scores)
{
    long row = blockIdx.x;
    float* p = scores + row * Nq;
    int tid = threadIdx.x;
    float v[4];
    float mx = -1e30f;
    #pragma unroll
    for (int t=0;t<4;t++) { v[t] = p[tid + t*256]; mx = fmaxf(mx, v[t]); }
    __shared__ float sm[8];
    #pragma unroll
    for (int o=16;o>0;o>>=1) mx = fmaxf(mx, __shfl_xor_sync(0xffffffffu, mx, o));
    if ((tid & 31) == 0) sm[tid>>5] = mx;
    __syncthreads();
    float m2 = sm[0];
    #pragma unroll
    for (int w=1;w<8;w++) m2 = fmaxf(m2, sm[w]);
    float s = 0.f;
    #pragma unroll
    for (int t=0;t<4;t++) { v[t] = __expf(v[t]-m2); s += v[t]; }
    #pragma unroll
    for (int o=16;o>0;o>>=1) s += __shfl_xor_sync(0xffffffffu, s, o);
    __syncthreads();
    if ((tid & 31) == 0) sm[tid>>5] = s;
    __syncthreads();
    float st = 0.f;
    #pragma unroll
    for (int w=0;w<8;w++) st += sm[w];
    float inv = 1.f/st;
    #pragma unroll
    for (int t=0;t<4;t++) p[tid + t*256] = v[t]*inv;
}

__global__ void pv_kernel(const float* __restrict__ scores, const float* __restrict__ qkv,
                          float* __restrict__ sa)
{
    __shared__ float Ps[64][33];
    __shared__ float Vs[32][33];
    int bh = blockIdx.y, b = bh >> 3, h = bh & 7;
    int i0 = blockIdx.x * 64;
    int tid = threadIdx.x;
    int d = tid & 31, ig = tid >> 5;
    int plr = tid >> 2, plj = (tid & 3) * 8;
    int vr = tid >> 3, vd = (tid & 7) * 4;
    float acc[8] = {};
    for (int j0 = 0; j0 < Nq; j0 += 32) {
        const float* ps = scores + ((long)bh*Nq + i0 + plr)*Nq + j0 + plj;
        #pragma unroll
        for (int t=0;t<8;t++) Ps[plr][plj+t] = ps[t];
        const float* vs = qkv + (long)(b*Nq + j0 + vr)*768 + 512 + h*32 + vd;
        #pragma unroll
        for (int t=0;t<4;t++) Vs[vr][vd+t] = vs[t];
        __syncthreads();
        #pragma unroll
        for (int jj=0;jj<32;jj++) {
            float vv = Vs[jj][d];
            #pragma unroll
            for (int r=0;r<8;r++) acc[r] += Ps[ig*8+r][jj]*vv;
        }
        __syncthreads();
    }
    #pragma unroll
    for (int r=0;r<8;r++)
        sa[(long)(b*Nq + i0 + ig*8 + r)*256 + h*32 + d] = acc[r];
}

// ---------------- residual + LayerNorm (optional transposed in/out) ----------------
__global__ void add_ln_kernel(const float* __restrict__ x, int x_t,
                              const float* __restrict__ y,
                              const float* __restrict__ g, const float* __restrict__ be,
                              float* __restrict__ out, int out_t)
{
    int bn = blockIdx.x, b = bn >> 10, n = bn & 1023;
    int c = threadIdx.x;
    float xv = x_t ? x[(long)(b*256 + c)*Nq + n] : x[(long)bn*256 + c];
    float v = xv + y[(long)bn*256 + c];
    __shared__ float s1[8], s2[8];
    float a = v, q = v*v;
    #pragma unroll
    for (int o=16;o>0;o>>=1) { a += __shfl_xor_sync(0xffffffffu, a, o); q += __shfl_xor_sync(0xffffffffu, q, o); }
    if ((c & 31) == 0) { s1[c>>5] = a; s2[c>>5] = q; }
    __syncthreads();
    float sa_ = 0.f, sq = 0.f;
    #pragma unroll
    for (int w=0;w<8;w++) { sa_ += s1[w]; sq += s2[w]; }
    float mean = sa_*(1.f/256.f);
    float var  = sq*(1.f/256.f) - mean*mean;
    float inv  = rsqrtf(var + 1e-5f);
    float o = (v - mean)*inv*g[c] + be[c];
    if (out_t) out[(long)(b*256 + c)*Nq + n] = o;
    else       out[(long)bn*256 + c] = o;
}

// ---------------- multi-scale deformable sampling ----------------
__global__ void deform_kernel(const float* __restrict__ off, const float* __restrict__ awr,
                              const float* __restrict__ qpos, float* __restrict__ ca)
{
    int bn = blockIdx.x, b = bn >> 10;
    int tid = threadIdx.x;       // tid = h*32 + d
    int h = tid >> 5;
    __shared__ float s_off[192], s_aw[96];
    if (tid < 192) s_off[tid] = off[(long)bn*192 + tid];
    if (tid < 96)  s_aw[tid]  = awr[(long)bn*96 + tid];
    __syncthreads();

    float wl[12];
    {
        float mx = -1e30f;
        #pragma unroll
        for (int t=0;t<12;t++) mx = fmaxf(mx, s_aw[h*12+t]);
        float s = 0.f;
        #pragma unroll
        for (int t=0;t<12;t++) { wl[t] = __expf(s_aw[h*12+t]-mx); s += wl[t]; }
        float inv = 1.f/s;
        #pragma unroll
        for (int t=0;t<12;t++) wl[t] *= inv;
    }
    float rx = qpos[(long)bn*2+0] * (1.f/352.f);
    float ry = qpos[(long)bn*2+1] * (1.f/400.f);
    float acc = 0.f;
    #pragma unroll
    for (int l = 0; l < 3; l++) {
        const int Hh = (l < 2) ? 200 : 400;
        const int Ww = (l < 2) ? 176 : 352;
        const long base = ((l == 0) ? VOFF0 : (l == 1) ? VOFF1 : VOFF2)
                          + (long)b * Hh * Ww * 256 + tid;
        float fx = rx * (float)Ww, fy = ry * (float)Hh;
        #pragma unroll
        for (int p = 0; p < 4; p++) {
            int oi = (h*12 + l*4 + p)*2;
            float x = fx + s_off[oi]   - 0.5f;
            float y = fy + s_off[oi+1] - 0.5f;
            float x0f = floorf(x), y0f = floorf(y);
            float wx = x - x0f, wy = y - y0f;
            float aw = wl[l*4+p];
            float w00 = (1.f-wx)*(1.f-wy)*aw, w10 = wx*(1.f-wy)*aw;
            float w01 = (1.f-wx)*wy*aw,       w11 = wx*wy*aw;
            bool vx0 = (x0f >= 0.f)  & (x0f <  (float)Ww);
            bool vx1 = (x0f >= -1.f) & (x0f <  (float)(Ww-1));
            bool vy0 = (y0f >= 0.f)  & (y0f <  (float)Hh);
            bool vy1 = (y0f >= -1.f) & (y0f <  (float)(Hh-1));
            if (vx0 | vx1) {
                int ix0 = (int)x0f;
                if (vy0 | vy1) {
                    int iy0 = (int)y0f;
                    if (vx0 && vy0) acc += w00 * g_values[base + (long)(iy0*Ww + ix0)*256];
                    if (vx1 && vy0) acc += w10 * g_values[base + (long)(iy0*Ww + ix0 + 1)*256];
                    if (vx0 && vy1) acc += w01 * g_values[base + (long)((iy0+1)*Ww + ix0)*256];
                    if (vx1 && vy1) acc += w11 * g_values[base + (long)((iy0+1)*Ww + ix0 + 1)*256];
                }
            }
        }
    }
    ca[(long)bn*256 + tid] = acc;
}

// ---------------- launch ----------------
extern "C" void kernel_launch(void* const* d_in, const int* in_sizes, int n_in,
                              void* d_out, int out_size)
{
    const float* query = (const float*)d_in[0];
    const float* qpos  = (const float*)d_in[1];
    const float* bev   = (const float*)d_in[2];
    const float* xc4   = (const float*)d_in[3];
    const float* xc3   = (const float*)d_in[4];
    const float* in_w  = (const float*)d_in[5];
    const float* in_b  = (const float*)d_in[6];
    const float* op_w  = (const float*)d_in[7];
    const float* op_b  = (const float*)d_in[8];
    const float* w_off = (const float*)d_in[9];
    const float* b_off = (const float*)d_in[10];
    const float* w_att = (const float*)d_in[11];
    const float* b_att = (const float*)d_in[12];
    const float* w_val = (const float*)d_in[13];
    const float* b_val = (const float*)d_in[14];
    const float* w_out = (const float*)d_in[15];
    const float* b_out = (const float*)d_in[16];
    const float* w_f1  = (const float*)d_in[17];
    const float* b_f1  = (const float*)d_in[18];
    const float* w_f2  = (const float*)d_in[19];
    const float* b_f2  = (const float*)d_in[20];
    const float* g1  = (const float*)d_in[21];
    const float* be1 = (const float*)d_in[22];
    const float* g2  = (const float*)d_in[23];
    const float* be2 = (const float*)d_in[24];
    const float* g3  = (const float*)d_in[25];
    const float* be3 = (const float*)d_in[26];
    float* out = (float*)d_out;
    (void)in_sizes; (void)n_in; (void)out_size;

    float *p_qkv, *p_scores, *p_sa, *p_tmp, *p_q1, *p_q2, *p_off, *p_aw, *p_ca, *p_val, *p_ffh;
    cudaGetSymbolAddress((void**)&p_qkv,    g_qkv);
    cudaGetSymbolAddress((void**)&p_scores, g_scores);
    cudaGetSymbolAddress((void**)&p_sa,     g_sa);
    cudaGetSymbolAddress((void**)&p_tmp,    g_tmp);
    cudaGetSymbolAddress((void**)&p_q1,     g_q1);
    cudaGetSymbolAddress((void**)&p_q2,     g_q2);
    cudaGetSymbolAddress((void**)&p_off,    g_off);
    cudaGetSymbolAddress((void**)&p_aw,     g_aw);
    cudaGetSymbolAddress((void**)&p_ca,     g_ca);
    cudaGetSymbolAddress((void**)&p_val,    g_values);
    cudaGetSymbolAddress((void**)&p_ffh,    g_ffh);

    // ---- value projections (the big GEMMs; 55.4 GFLOP total) ----
    gemm_at_kernel<<<dim3(HW0/128, 2, 2), 256>>>(bev, w_val, b_val, p_val+VOFF0,
                                                 HW0, 256, 256, 256L*HW0, (long)HW0*256);
    gemm_at_kernel<<<dim3(HW0/128, 2, 2), 256>>>(xc4, w_val, b_val, p_val+VOFF1,
                                                 HW0, 256, 256, 256L*HW0, (long)HW0*256);
    gemm_at_kernel<<<dim3(HW2/128, 2, 2), 256>>>(xc3, w_val, b_val, p_val+VOFF2,
                                                 HW2, 256, 256, 256L*HW2, (long)HW2*256);

    // ---- self-attention ----
    gemm_at_kernel<<<dim3(8, 6, 2), 256>>>(query, in_w, in_b, p_qkv,
                                           1024, 768, 256, 256L*1024, 1024L*768);
    scores_kernel<<<dim3(16, 16, 16), 256>>>(p_qkv, p_scores);
    softmax_kernel<<<16384, 256>>>(p_scores);
    pv_kernel<<<dim3(16, 16), 256>>>(p_scores, p_qkv, p_sa);
    gemm_a_kernel<<<dim3(16, 2), 256>>>(p_sa, op_w, op_b, p_tmp, 2048, 256, 256, 0);
    add_ln_kernel<<<2048, 256>>>(query, 1, p_tmp, g1, be1, p_q1, 0);

    // ---- deformable cross-attention ----
    gemm_a_kernel<<<dim3(16, 2), 256>>>(p_q1, w_off, b_off, p_off, 2048, 192, 256, 0);
    gemm_a_kernel<<<dim3(16, 1), 256>>>(p_q1, w_att, b_att, p_aw, 2048, 96, 256, 0);
    deform_kernel<<<2048, 256>>>(p_off, p_aw, qpos, p_ca);
    gemm_a_kernel<<<dim3(16, 2), 256>>>(p_ca, w_out, b_out, p_tmp, 2048, 256, 256, 0);
    add_ln_kernel<<<2048, 256>>>(p_q1, 0, p_tmp, g2, be2, p_q2, 0);

    // ---- FFN ----
    gemm_a_kernel<<<dim3(16, 16), 256>>>(p_q2, w_f1, b_f1, p_ffh, 2048, 2048, 256, 1);
    gemm_a_kernel<<<dim3(16, 2), 256>>>(p_ffh, w_f2, b_f2, p_tmp, 2048, 256, 2048, 0);
    add_ln_kernel<<<2048, 256>>>(p_q2, 0, p_tmp, g3, be3, out, 1);
}

// round 7
// speedup vs baseline: 3.0989x; 3.0989x over previous
#include <cuda_runtime.h>
#include <stdint.h>
#include <math.h>

// Problem constants
#define Bq 2
#define Nq 1024
#define Cc 256
#define NH 8
#define DH 32
#define FF 2048
#define HW0 35200   // 200x176
#define HW2 140800  // 400x352

// value buffer offsets (in floats), layout per level: [B, HW, 256]
#define VOFF0 0L
#define VOFF1 (2L*35200*256)
#define VOFF2 (2L*(35200+35200)*256)
#define VTOT  (2L*(35200+35200+140800)*256)

// ---------------- scratch (static device globals; no allocation) ----------------
__device__ float g_qkv[Bq*Nq*3*Cc];
__device__ float g_scores[(long)Bq*NH*Nq*Nq];   // 64 MB
__device__ float g_sa[Bq*Nq*Cc];
__device__ float g_tmp[Bq*Nq*Cc];
__device__ float g_q1[Bq*Nq*Cc];
__device__ float g_q2[Bq*Nq*Cc];
__device__ float g_off[Bq*Nq*192];
__device__ float g_aw[Bq*Nq*96];
__device__ float g_ca[Bq*Nq*Cc];
__device__ float g_ffh[Bq*Nq*FF];
__device__ float g_values[VTOT];                // 432 MB

// =====================================================================
// tf32 mma.sync value-projection GEMM (baseline PTX, no 'a' features)
//   Out[pix, n] = sum_k Feat[k, pix] * W[n, k] + bias[n]
//   CTA tile: 128 pix x 128 n, K = 256.
//   B tile (128 n x 256 k) staged once in smem, [n][k] stride 260.
//   A chunks (32 k x 128 pix) double-buffered via cp.async, [k][pix] stride 136.
// =====================================================================

#define VB_WORDS   (128*260)        // 33280 words
#define VA_WORDS   (32*136)         // 4352 words per buffer
#define VG_SMEM_B  ((VB_WORDS + 2*VA_WORDS) * 4)   // 167936 bytes

__device__ __forceinline__ void mma_tf32_16x8x8(float* c, const uint32_t* a, const uint32_t* b) {
    asm volatile(
        "mma.sync.aligned.m16n8k8.row.col.f32.tf32.tf32.f32 "
        "{%0,%1,%2,%3}, {%4,%5,%6,%7}, {%8,%9}, {%0,%1,%2,%3};"
        : "+f"(c[0]), "+f"(c[1]), "+f"(c[2]), "+f"(c[3])
        : "r"(a[0]), "r"(a[1]), "r"(a[2]), "r"(a[3]), "r"(b[0]), "r"(b[1]));
}

__global__ __launch_bounds__(256, 1)
void val_gemm_mma(const float* __restrict__ feat, const float* __restrict__ W,
                  const float* __restrict__ bias, float* __restrict__ outp, int HW)
{
    extern __shared__ float sm[];
    float* Bs = sm;                       // [128][260]
    float* As = sm + VB_WORDS;            // [2][32][136]
    const uint32_t* Bsu = (const uint32_t*)Bs;
    const uint32_t* Asu = (const uint32_t*)As;

    int tid  = threadIdx.x;
    int lane = tid & 31, wid = tid >> 5;
    int g = lane >> 2, tig = lane & 3;
    int wm = wid >> 2;           // 0..1  (64-row half)
    int wn = wid & 3;            // 0..3  (32-col quarter)
    long pix0 = (long)blockIdx.x * 128;
    int  n0   = blockIdx.y * 128;
    int  bz   = blockIdx.z;

    const float* fb = feat + (long)bz * 256 * HW;

    // ---- stage B tile [128 n][256 k] (natural layout, coalesced) ----
    #pragma unroll 8
    for (int i = 0; i < 32; i++) {
        int f4 = tid + 256 * i;
        int nl = f4 >> 6;            // 64 float4 per n-row
        int kq = f4 & 63;
        float4 v = *(const float4*)(W + (long)(n0 + nl) * 256 + kq * 4);
        *(float4*)(Bs + nl * 260 + kq * 4) = v;
    }

    // ---- prologue: async-load A chunks 0 and 1 ----
    uint32_t as_base = (uint32_t)__cvta_generic_to_shared(As);
    #pragma unroll
    for (int c = 0; c < 2; c++) {
        #pragma unroll
        for (int i = 0; i < 4; i++) {
            int f4 = tid + 256 * i;
            int kl = f4 >> 5;        // 32 float4 per k-row
            int p4 = f4 & 31;
            const float* src = fb + (long)(c * 32 + kl) * HW + pix0 + p4 * 4;
            uint32_t dst = as_base + (uint32_t)((c * VA_WORDS + kl * 136 + p4 * 4) * 4);
            asm volatile("cp.async.cg.shared.global [%0], [%1], 16;" :: "r"(dst), "l"(src) : "memory");
        }
        asm volatile("cp.async.commit_group;" ::: "memory");
    }

    float acc[4][4][4];
    #pragma unroll
    for (int mt = 0; mt < 4; mt++)
        #pragma unroll
        for (int nt = 0; nt < 4; nt++)
            #pragma unroll
            for (int q = 0; q < 4; q++) acc[mt][nt][q] = 0.f;

    int mbase = wm * 64;
    int nbw   = wn * 32;

    for (int c = 0; c < 8; c++) {
        if (c < 6) { asm volatile("cp.async.wait_group 1;" ::: "memory"); }
        else       { asm volatile("cp.async.wait_group 0;" ::: "memory"); }
        __syncthreads();

        const uint32_t* A = Asu + (c & 1) * VA_WORDS;
        const uint32_t* B = Bsu + c * 32;
        #pragma unroll
        for (int s = 0; s < 4; s++) {
            int k0 = s * 8;
            uint32_t af[4][4];
            #pragma unroll
            for (int mt = 0; mt < 4; mt++) {
                int m = mbase + mt * 16 + g;
                const uint32_t* ar  = A + (k0 + tig) * 136 + m;
                const uint32_t* ar2 = A + (k0 + tig + 4) * 136 + m;
                af[mt][0] = ar[0];  af[mt][1] = ar[8];
                af[mt][2] = ar2[0]; af[mt][3] = ar2[8];
            }
            uint32_t bf[4][2];
            #pragma unroll
            for (int nt = 0; nt < 4; nt++) {
                const uint32_t* br = B + (nbw + nt * 8 + g) * 260 + k0 + tig;
                bf[nt][0] = br[0]; bf[nt][1] = br[4];
            }
            #pragma unroll
            for (int mt = 0; mt < 4; mt++)
                #pragma unroll
                for (int nt = 0; nt < 4; nt++)
                    mma_tf32_16x8x8(acc[mt][nt], af[mt], bf[nt]);
        }
        __syncthreads();

        if (c < 6) {
            int cn = c + 2;
            #pragma unroll
            for (int i = 0; i < 4; i++) {
                int f4 = tid + 256 * i;
                int kl = f4 >> 5;
                int p4 = f4 & 31;
                const float* src = fb + (long)(cn * 32 + kl) * HW + pix0 + p4 * 4;
                uint32_t dst = as_base + (uint32_t)(((c & 1) * VA_WORDS + kl * 136 + p4 * 4) * 4);
                asm volatile("cp.async.cg.shared.global [%0], [%1], 16;" :: "r"(dst), "l"(src) : "memory");
            }
            asm volatile("cp.async.commit_group;" ::: "memory");
        }
    }

    // ---- epilogue: bias + float2 stores into [pix, 256] ----
    float* ob = outp + (long)bz * HW * 256;
    #pragma unroll
    for (int nt = 0; nt < 4; nt++) {
        int nc = n0 + nbw + nt * 8 + tig * 2;
        float b0 = bias[nc], b1 = bias[nc + 1];
        #pragma unroll
        for (int mt = 0; mt < 4; mt++) {
            long r = pix0 + mbase + mt * 16 + g;
            float2 v0 = make_float2(acc[mt][nt][0] + b0, acc[mt][nt][1] + b1);
            float2 v1 = make_float2(acc[mt][nt][2] + b0, acc[mt][nt][3] + b1);
            *(float2*)(ob + r * 256 + nc)       = v0;
            *(float2*)(ob + (r + 8) * 256 + nc) = v1;
        }
    }
}

// ---------------- f32x2 packed FMA SIMT GEMM (small GEMMs) ----------------
union F2 { float2 f; unsigned long long u; };

__device__ __forceinline__ void ffma2(F2& d, const F2& a, const F2& b) {
    asm("fma.rn.f32x2 %0, %1, %2, %0;" : "+l"(d.u) : "l"(a.u), "l"(b.u));
}

#define TM 128
#define TN 128
#define TK 16
#define SROW 132

__device__ __forceinline__ void mm_inner(const float (&As)[TK][SROW],
                                         const float (&Bs)[TK][SROW],
                                         F2 (&acc)[4][8], int tx, int ty)
{
    #pragma unroll
    for (int kk = 0; kk < TK; kk++) {
        float4 a0 = *(const float4*)&As[kk][ty*8];
        float4 a1 = *(const float4*)&As[kk][ty*8+4];
        float4 b0 = *(const float4*)&Bs[kk][tx*8];
        float4 b1 = *(const float4*)&Bs[kk][tx*8+4];
        F2 a2[4];
        a2[0].f = make_float2(a0.x, a0.y);
        a2[1].f = make_float2(a0.z, a0.w);
        a2[2].f = make_float2(a1.x, a1.y);
        a2[3].f = make_float2(a1.z, a1.w);
        float bv[8] = {b0.x,b0.y,b0.z,b0.w,b1.x,b1.y,b1.z,b1.w};
        #pragma unroll
        for (int j = 0; j < 8; j++) {
            F2 bd; bd.f = make_float2(bv[j], bv[j]);
            #pragma unroll
            for (int i = 0; i < 4; i++) ffma2(acc[i][j], a2[i], bd);
        }
    }
}

// Out[m,n] = sum_k A[k*M+m] * W[n*K+k] + bias[n].  A stored K-major.
__global__ __launch_bounds__(256, 2)
void gemm_at_kernel(const float* __restrict__ A, const float* __restrict__ W,
                    const float* __restrict__ bias, float* __restrict__ Out,
                    int M, int Nc, int K, long sA, long sO)
{
    __shared__ float As[TK][SROW];
    __shared__ float Bs[TK][SROW];
    const float* Ab = A + (long)blockIdx.z * sA;
    float* Ob = Out + (long)blockIdx.z * sO;
    int m0 = blockIdx.x * TM, n0 = blockIdx.y * TN;
    int tid = threadIdx.x;
    int tx = tid & 15, ty = tid >> 4;
    int a_c4 = (tid & 31) * 4, a_r = tid >> 5;
    int b_j = tid >> 1, b_k = (tid & 1) * 8;
    int jglob = n0 + b_j;

    F2 acc[4][8];
    #pragma unroll
    for (int i=0;i<4;i++)
        #pragma unroll
        for (int j=0;j<8;j++) { acc[i][j].f.x = 0.f; acc[i][j].f.y = 0.f; }

    for (int k0 = 0; k0 < K; k0 += TK) {
        #pragma unroll
        for (int r = 0; r < 2; r++) {
            int kk = a_r + r*8;
            float4 v = *(const float4*)(Ab + (long)(k0+kk)*M + m0 + a_c4);
            *(float4*)&As[kk][a_c4] = v;
        }
        if (jglob < Nc) {
            const float* src = W + (long)jglob*K + k0 + b_k;
            #pragma unroll
            for (int t=0;t<8;t++) Bs[b_k+t][b_j] = src[t];
        } else {
            #pragma unroll
            for (int t=0;t<8;t++) Bs[b_k+t][b_j] = 0.f;
        }
        __syncthreads();
        mm_inner(As, Bs, acc, tx, ty);
        __syncthreads();
    }
    #pragma unroll
    for (int i=0;i<4;i++) {
        int m = m0 + ty*8 + 2*i;
        #pragma unroll
        for (int j=0;j<8;j++) {
            int n = n0 + tx*8 + j;
            if (n < Nc) {
                float bb = bias[n];
                Ob[(long)m*Nc + n]     = acc[i][j].f.x + bb;
                Ob[(long)(m+1)*Nc + n] = acc[i][j].f.y + bb;
            }
        }
    }
}

// Out[m,n] = sum_k A[m*K+k] * W[n*K+k] + bias[n], optional ReLU. A row-major.
__global__ __launch_bounds__(256, 2)
void gemm_a_kernel(const float* __restrict__ A, const float* __restrict__ W,
                   const float* __restrict__ bias, float* __restrict__ Out,
                   int M, int Nc, int K, int relu)
{
    __shared__ float As[TK][SROW];
    __shared__ float Bs[TK][SROW];
    int m0 = blockIdx.x * TM, n0 = blockIdx.y * TN;
    int tid = threadIdx.x;
    int tx = tid & 15, ty = tid >> 4;
    int a_m = tid >> 1, a_k = (tid & 1) * 8;
    int b_j = tid >> 1, b_k = (tid & 1) * 8;
    int jglob = n0 + b_j;

    F2 acc[4][8];
    #pragma unroll
    for (int i=0;i<4;i++)
        #pragma unroll
        for (int j=0;j<8;j++) { acc[i][j].f.x = 0.f; acc[i][j].f.y = 0.f; }

    for (int k0 = 0; k0 < K; k0 += TK) {
        {
            const float* src = A + (long)(m0 + a_m)*K + k0 + a_k;
            #pragma unroll
            for (int t=0;t<8;t++) As[a_k+t][a_m] = src[t];
        }
        if (jglob < Nc) {
            const float* src = W + (long)jglob*K + k0 + b_k;
            #pragma unroll
            for (int t=0;t<8;t++) Bs[b_k+t][b_j] = src[t];
        } else {
            #pragma unroll
            for (int t=0;t<8;t++) Bs[b_k+t][b_j] = 0.f;
        }
        __syncthreads();
        mm_inner(As, Bs, acc, tx, ty);
        __syncthreads();
    }
    #pragma unroll
    for (int i=0;i<4;i++) {
        int m = m0 + ty*8 + 2*i;
        #pragma unroll
        for (int j=0;j<8;j++) {
            int n = n0 + tx*8 + j;
            if (n < Nc) {
                float bb = bias[n];
                float v0 = acc[i][j].f.x + bb;
                float v1 = acc[i][j].f.y + bb;
                if (relu) { v0 = fmaxf(v0, 0.f); v1 = fmaxf(v1, 0.f); }
                Out[(long)m*Nc + n]     = v0;
                Out[(long)(m+1)*Nc + n] = v1;
            }
        }
    }
}

// ---------------- attention: scores, softmax, P@V ----------------
__global__ void scores_kernel(const float* __restrict__ qkv, float* __restrict__ scores)
{
    __shared__ float Qs[64][33];
    __shared__ float Ks[64][33];
    int bh = blockIdx.z, b = bh >> 3, h = bh & 7;
    int i0 = blockIdx.x * 64, j0 = blockIdx.y * 64;
    int tid = threadIdx.x;
    int lr = tid >> 2, ld = (tid & 3) * 8;
    {
        const float* qsrc = qkv + (long)(b*Nq + i0 + lr)*768 + h*32 + ld;
        const float* ksrc = qkv + (long)(b*Nq + j0 + lr)*768 + 256 + h*32 + ld;
        #pragma unroll
        for (int t=0;t<8;t++) { Qs[lr][ld+t] = qsrc[t]; Ks[lr][ld+t] = ksrc[t]; }
    }
    __syncthreads();
    int tx = tid & 15, ty = tid >> 4;
    float acc[4][4] = {};
    #pragma unroll
    for (int d = 0; d < 32; d++) {
        float a[4], bb[4];
        #pragma unroll
        for (int i=0;i<4;i++) a[i] = Qs[ty*4+i][d];
        #pragma unroll
        for (int j=0;j<4;j++) bb[j] = Ks[tx*4+j][d];
        #pragma unroll
        for (int i=0;i<4;i++)
            #pragma unroll
            for (int j=0;j<4;j++) acc[i][j] += a[i]*bb[j];
    }
    const float sc = 0.17677669529663689f; // 1/sqrt(32)
    #pragma unroll
    for (int i=0;i<4;i++)
        #pragma unroll
        for (int j=0;j<4;j++)
            scores[((long)bh*Nq + i0 + ty*4 + i)*Nq + j0 + tx*4 + j] = acc[i][j]*sc;
}

__global__ void softmax_kernel(float* __restrict__ scores)
{
    long row = blockIdx.x;
    float* p = scores + row * Nq;
    int tid = threadIdx.x;
    float v[4];
    float mx = -1e30f;
    #pragma unroll
    for (int t=0;t<4;t++) { v[t] = p[tid + t*256]; mx = fmaxf(mx, v[t]); }
    __shared__ float sm[8];
    #pragma unroll
    for (int o=16;o>0;o>>=1) mx = fmaxf(mx, __shfl_xor_sync(0xffffffffu, mx, o));
    if ((tid & 31) == 0) sm[tid>>5] = mx;
    __syncthreads();
    float m2 = sm[0];
    #pragma unroll
    for (int w=1;w<8;w++) m2 = fmaxf(m2, sm[w]);
    float s = 0.f;
    #pragma unroll
    for (int t=0;t<4;t++) { v[t] = __expf(v[t]-m2); s += v[t]; }
    #pragma unroll
    for (int o=16;o>0;o>>=1) s += __shfl_xor_sync(0xffffffffu, s, o);
    __syncthreads();
    if ((tid & 31) == 0) sm[tid>>5] = s;
    __syncthreads();
    float st = 0.f;
    #pragma unroll
    for (int w=0;w<8;w++) st += sm[w];
    float inv = 1.f/st;
    #pragma unroll
    for (int t=0;t<4;t++) p[tid + t*256] = v[t]*inv;
}

__global__ void pv_kernel(const float* __restrict__ scores, const float* __restrict__ qkv,
                          float* __restrict__ sa)
{
    __shared__ float Ps[64][33];
    __shared__ float Vs[32][33];
    int bh = blockIdx.y, b = bh >> 3, h = bh & 7;
    int i0 = blockIdx.x * 64;
    int tid = threadIdx.x;
    int d = tid & 31, ig = tid >> 5;
    int plr = tid >> 2, plj = (tid & 3) * 8;
    int vr = tid >> 3, vd = (tid & 7) * 4;
    float acc[8] = {};
    for (int j0 = 0; j0 < Nq; j0 += 32) {
        const float* ps = scores + ((long)bh*Nq + i0 + plr)*Nq + j0 + plj;
        #pragma unroll
        for (int t=0;t<8;t++) Ps[plr][plj+t] = ps[t];
        const float* vs = qkv + (long)(b*Nq + j0 + vr)*768 + 512 + h*32 + vd;
        #pragma unroll
        for (int t=0;t<4;t++) Vs[vr][vd+t] = vs[t];
        __syncthreads();
        #pragma unroll
        for (int jj=0;jj<32;jj++) {
            float vv = Vs[jj][d];
            #pragma unroll
            for (int r=0;r<8;r++) acc[r] += Ps[ig*8+r][jj]*vv;
        }
        __syncthreads();
    }
    #pragma unroll
    for (int r=0;r<8;r++)
        sa[(long)(b*Nq + i0 + ig*8 + r)*256 + h*32 + d] = acc[r];
}

// ---------------- residual + LayerNorm (optional transposed in/out) ----------------
__global__ void add_ln_kernel(const float* __restrict__ x, int x_t,
                              const float* __restrict__ y,
                              const float* __restrict__ g, const float* __restrict__ be,
                              float* __restrict__ out, int out_t)
{
    int bn = blockIdx.x, b = bn >> 10, n = bn & 1023;
    int c = threadIdx.x;
    float xv = x_t ? x[(long)(b*256 + c)*Nq + n] : x[(long)bn*256 + c];
    float v = xv + y[(long)bn*256 + c];
    __shared__ float s1[8], s2[8];
    float a = v, q = v*v;
    #pragma unroll
    for (int o=16;o>0;o>>=1) { a += __shfl_xor_sync(0xffffffffu, a, o); q += __shfl_xor_sync(0xffffffffu, q, o); }
    if ((c & 31) == 0) { s1[c>>5] = a; s2[c>>5] = q; }
    __syncthreads();
    float sa_ = 0.f, sq = 0.f;
    #pragma unroll
    for (int w=0;w<8;w++) { sa_ += s1[w]; sq += s2[w]; }
    float mean = sa_*(1.f/256.f);
    float var  = sq*(1.f/256.f) - mean*mean;
    float inv  = rsqrtf(var + 1e-5f);
    float o = (v - mean)*inv*g[c] + be[c];
    if (out_t) out[(long)(b*256 + c)*Nq + n] = o;
    else       out[(long)bn*256 + c] = o;
}

// ---------------- multi-scale deformable sampling ----------------
__global__ void deform_kernel(const float* __restrict__ off, const float* __restrict__ awr,
                              const float* __restrict__ qpos, float* __restrict__ ca)
{
    int bn = blockIdx.x, b = bn >> 10;
    int tid = threadIdx.x;       // tid = h*32 + d
    int h = tid >> 5;
    __shared__ float s_off[192], s_aw[96];
    if (tid < 192) s_off[tid] = off[(long)bn*192 + tid];
    if (tid < 96)  s_aw[tid]  = awr[(long)bn*96 + tid];
    __syncthreads();

    float wl[12];
    {
        float mx = -1e30f;
        #pragma unroll
        for (int t=0;t<12;t++) mx = fmaxf(mx, s_aw[h*12+t]);
        float s = 0.f;
        #pragma unroll
        for (int t=0;t<12;t++) { wl[t] = __expf(s_aw[h*12+t]-mx); s += wl[t]; }
        float inv = 1.f/s;
        #pragma unroll
        for (int t=0;t<12;t++) wl[t] *= inv;
    }
    float rx = qpos[(long)bn*2+0] * (1.f/352.f);
    float ry = qpos[(long)bn*2+1] * (1.f/400.f);
    float acc = 0.f;
    #pragma unroll
    for (int l = 0; l < 3; l++) {
        const int Hh = (l < 2) ? 200 : 400;
        const int Ww = (l < 2) ? 176 : 352;
        const long base = ((l == 0) ? VOFF0 : (l == 1) ? VOFF1 : VOFF2)
                          + (long)b * Hh * Ww * 256 + tid;
        float fx = rx * (float)Ww, fy = ry * (float)Hh;
        #pragma unroll
        for (int p = 0; p < 4; p++) {
            int oi = (h*12 + l*4 + p)*2;
            float x = fx + s_off[oi]   - 0.5f;
            float y = fy + s_off[oi+1] - 0.5f;
            float x0f = floorf(x), y0f = floorf(y);
            float wx = x - x0f, wy = y - y0f;
            float aw = wl[l*4+p];
            float w00 = (1.f-wx)*(1.f-wy)*aw, w10 = wx*(1.f-wy)*aw;
            float w01 = (1.f-wx)*wy*aw,       w11 = wx*wy*aw;
            bool vx0 = (x0f >= 0.f)  & (x0f <  (float)Ww);
            bool vx1 = (x0f >= -1.f) & (x0f <  (float)(Ww-1));
            bool vy0 = (y0f >= 0.f)  & (y0f <  (float)Hh);
            bool vy1 = (y0f >= -1.f) & (y0f <  (float)(Hh-1));
            if (vx0 | vx1) {
                int ix0 = (int)x0f;
                if (vy0 | vy1) {
                    int iy0 = (int)y0f;
                    if (vx0 && vy0) acc += w00 * g_values[base + (long)(iy0*Ww + ix0)*256];
                    if (vx1 && vy0) acc += w10 * g_values[base + (long)(iy0*Ww + ix0 + 1)*256];
                    if (vx0 && vy1) acc += w01 * g_values[base + (long)((iy0+1)*Ww + ix0)*256];
                    if (vx1 && vy1) acc += w11 * g_values[base + (long)((iy0+1)*Ww + ix0 + 1)*256];
                }
            }
        }
    }
    ca[(long)bn*256 + tid] = acc;
}

// ---------------- launch ----------------
extern "C" void kernel_launch(void* const* d_in, const int* in_sizes, int n_in,
                              void* d_out, int out_size)
{
    const float* query = (const float*)d_in[0];
    const float* qpos  = (const float*)d_in[1];
    const float* bev   = (const float*)d_in[2];
    const float* xc4   = (const float*)d_in[3];
    const float* xc3   = (const float*)d_in[4];
    const float* in_w  = (const float*)d_in[5];
    const float* in_b  = (const float*)d_in[6];
    const float* op_w  = (const float*)d_in[7];
    const float* op_b  = (const float*)d_in[8];
    const float* w_off = (const float*)d_in[9];
    const float* b_off = (const float*)d_in[10];
    const float* w_att = (const float*)d_in[11];
    const float* b_att = (const float*)d_in[12];
    const float* w_val = (const float*)d_in[13];
    const float* b_val = (const float*)d_in[14];
    const float* w_out = (const float*)d_in[15];
    const float* b_out = (const float*)d_in[16];
    const float* w_f1  = (const float*)d_in[17];
    const float* b_f1  = (const float*)d_in[18];
    const float* w_f2  = (const float*)d_in[19];
    const float* b_f2  = (const float*)d_in[20];
    const float* g1  = (const float*)d_in[21];
    const float* be1 = (const float*)d_in[22];
    const float* g2  = (const float*)d_in[23];
    const float* be2 = (const float*)d_in[24];
    const float* g3  = (const float*)d_in[25];
    const float* be3 = (const float*)d_in[26];
    float* out = (float*)d_out;
    (void)in_sizes; (void)n_in; (void)out_size;

    float *p_qkv, *p_scores, *p_sa, *p_tmp, *p_q1, *p_q2, *p_off, *p_aw, *p_ca, *p_val, *p_ffh;
    cudaGetSymbolAddress((void**)&p_qkv,    g_qkv);
    cudaGetSymbolAddress((void**)&p_scores, g_scores);
    cudaGetSymbolAddress((void**)&p_sa,     g_sa);
    cudaGetSymbolAddress((void**)&p_tmp,    g_tmp);
    cudaGetSymbolAddress((void**)&p_q1,     g_q1);
    cudaGetSymbolAddress((void**)&p_q2,     g_q2);
    cudaGetSymbolAddress((void**)&p_off,    g_off);
    cudaGetSymbolAddress((void**)&p_aw,     g_aw);
    cudaGetSymbolAddress((void**)&p_ca,     g_ca);
    cudaGetSymbolAddress((void**)&p_val,    g_values);
    cudaGetSymbolAddress((void**)&p_ffh,    g_ffh);

    // ---- value projections on tf32 mma.sync (55.4 GFLOP) ----
    cudaFuncSetAttribute(val_gemm_mma, cudaFuncAttributeMaxDynamicSharedMemorySize, VG_SMEM_B);
    val_gemm_mma<<<dim3(HW0/128, 2, 2), 256, VG_SMEM_B>>>(bev, w_val, b_val, p_val + VOFF0, HW0);
    val_gemm_mma<<<dim3(HW0/128, 2, 2), 256, VG_SMEM_B>>>(xc4, w_val, b_val, p_val + VOFF1, HW0);
    val_gemm_mma<<<dim3(HW2/128, 2, 2), 256, VG_SMEM_B>>>(xc3, w_val, b_val, p_val + VOFF2, HW2);

    // ---- self-attention ----
    gemm_at_kernel<<<dim3(8, 6, 2), 256>>>(query, in_w, in_b, p_qkv,
                                           1024, 768, 256, 256L*1024, 1024L*768);
    scores_kernel<<<dim3(16, 16, 16), 256>>>(p_qkv, p_scores);
    softmax_kernel<<<16384, 256>>>(p_scores);
    pv_kernel<<<dim3(16, 16), 256>>>(p_scores, p_qkv, p_sa);
    gemm_a_kernel<<<dim3(16, 2), 256>>>(p_sa, op_w, op_b, p_tmp, 2048, 256, 256, 0);
    add_ln_kernel<<<2048, 256>>>(query, 1, p_tmp, g1, be1, p_q1, 0);

    // ---- deformable cross-attention ----
    gemm_a_kernel<<<dim3(16, 2), 256>>>(p_q1, w_off, b_off, p_off, 2048, 192, 256, 0);
    gemm_a_kernel<<<dim3(16, 1), 256>>>(p_q1, w_att, b_att, p_aw, 2048, 96, 256, 0);
    deform_kernel<<<2048, 256>>>(p_off, p_aw, qpos, p_ca);
    gemm_a_kernel<<<dim3(16, 2), 256>>>(p_ca, w_out, b_out, p_tmp, 2048, 256, 256, 0);
    add_ln_kernel<<<2048, 256>>>(p_q1, 0, p_tmp, g2, be2, p_q2, 0);

    // ---- FFN ----
    gemm_a_kernel<<<dim3(16, 16), 256>>>(p_q2, w_f1, b_f1, p_ffh, 2048, 2048, 256, 1);
    gemm_a_kernel<<<dim3(16, 2), 256>>>(p_ffh, w_f2, b_f2, p_tmp, 2048, 256, 2048, 0);
    add_ln_kernel<<<2048, 256>>>(p_q2, 0, p_tmp, g3, be3, out, 1);
}

// round 8
// speedup vs baseline: 5.7829x; 1.8661x over previous
#include <cuda_runtime.h>
#include <stdint.h>
#include <math.h>

// Problem constants
#define Bq 2
#define Nq 1024
#define Cc 256
#define NH 8
#define DH 32
#define FF 2048
#define HW0 35200   // 200x176
#define HW2 140800  // 400x352

// value buffer offsets (in floats), layout per level: [B, HW, 256]
#define VOFF0 0L
#define VOFF1 (2L*35200*256)
#define VOFF2 (2L*(35200+35200)*256)
#define VTOT  (2L*(35200+35200+140800)*256)

// ---------------- scratch (static device globals; no allocation) ----------------
__device__ float g_qkv[Bq*Nq*3*Cc];
__device__ float g_scores[(long)Bq*NH*Nq*Nq];   // 64 MB
__device__ float g_sa[Bq*Nq*Cc];
__device__ float g_tmp[Bq*Nq*Cc];
__device__ float g_q1[Bq*Nq*Cc];
__device__ float g_q2[Bq*Nq*Cc];
__device__ float g_off[Bq*Nq*192];
__device__ float g_aw[Bq*Nq*96];
__device__ float g_ca[Bq*Nq*Cc];
__device__ float g_ffh[Bq*Nq*FF];
__device__ float g_values[VTOT];                // 432 MB

__device__ __forceinline__ void mma_tf32_16x8x8(float* c, const uint32_t* a, const uint32_t* b) {
    asm volatile(
        "mma.sync.aligned.m16n8k8.row.col.f32.tf32.tf32.f32 "
        "{%0,%1,%2,%3}, {%4,%5,%6,%7}, {%8,%9}, {%0,%1,%2,%3};"
        : "+f"(c[0]), "+f"(c[1]), "+f"(c[2]), "+f"(c[3])
        : "r"(a[0]), "r"(a[1]), "r"(a[2]), "r"(a[3]), "r"(b[0]), "r"(b[1]));
}

#define CP_ASYNC16(dst, src) \
    asm volatile("cp.async.cg.shared.global [%0], [%1], 16;" :: "r"(dst), "l"(src) : "memory")
#define CP_ASYNC16Z(dst, src, sz) \
    asm volatile("cp.async.cg.shared.global [%0], [%1], 16, %2;" :: "r"(dst), "l"(src), "r"(sz) : "memory")
#define CP_COMMIT() asm volatile("cp.async.commit_group;" ::: "memory")
#define CP_WAIT1()  asm volatile("cp.async.wait_group 1;" ::: "memory")
#define CP_WAIT0()  asm volatile("cp.async.wait_group 0;" ::: "memory")

// =====================================================================
// gemm_mma_at: A K-major [K=256][M] (k-stride = M), W [N,256] row-major.
//   Out[bz*M*ldo + m*ldo + n] = sum_k A[bz*256*M + k*M + m] * W[n*256+k] + bias[n]
//   CTA tile 128m x 128n; B staged once; A double-buffered 32-k chunks.
// =====================================================================

#define VB_WORDS   (128*260)
#define VA_WORDS   (32*136)
#define VG_SMEM_B  ((VB_WORDS + 2*VA_WORDS) * 4)   // 167936 bytes

__global__ __launch_bounds__(256, 1)
void gemm_mma_at(const float* __restrict__ feat, const float* __restrict__ W,
                 const float* __restrict__ bias, float* __restrict__ outp,
                 int HW, int ldo)
{
    extern __shared__ float sm[];
    float* Bs = sm;                       // [128][260]
    float* As = sm + VB_WORDS;            // [2][32][136]
    const uint32_t* Bsu = (const uint32_t*)Bs;
    const uint32_t* Asu = (const uint32_t*)As;

    int tid  = threadIdx.x;
    int lane = tid & 31, wid = tid >> 5;
    int g = lane >> 2, tig = lane & 3;
    int wm = wid >> 2;
    int wn = wid & 3;
    long pix0 = (long)blockIdx.x * 128;
    int  n0   = blockIdx.y * 128;
    int  bz   = blockIdx.z;

    const float* fb = feat + (long)bz * 256 * HW;

    // ---- stage B tile [128 n][256 k] ----
    #pragma unroll 8
    for (int i = 0; i < 32; i++) {
        int f4 = tid + 256 * i;
        int nl = f4 >> 6;
        int kq = f4 & 63;
        float4 v = *(const float4*)(W + (long)(n0 + nl) * 256 + kq * 4);
        *(float4*)(Bs + nl * 260 + kq * 4) = v;
    }

    uint32_t as_base = (uint32_t)__cvta_generic_to_shared(As);
    #pragma unroll
    for (int c = 0; c < 2; c++) {
        #pragma unroll
        for (int i = 0; i < 4; i++) {
            int f4 = tid + 256 * i;
            int kl = f4 >> 5;
            int p4 = f4 & 31;
            const float* src = fb + (long)(c * 32 + kl) * HW + pix0 + p4 * 4;
            uint32_t dst = as_base + (uint32_t)((c * VA_WORDS + kl * 136 + p4 * 4) * 4);
            CP_ASYNC16(dst, src);
        }
        CP_COMMIT();
    }

    float acc[4][4][4];
    #pragma unroll
    for (int mt = 0; mt < 4; mt++)
        #pragma unroll
        for (int nt = 0; nt < 4; nt++)
            #pragma unroll
            for (int q = 0; q < 4; q++) acc[mt][nt][q] = 0.f;

    int mbase = wm * 64;
    int nbw   = wn * 32;

    for (int c = 0; c < 8; c++) {
        if (c < 6) { CP_WAIT1(); } else { CP_WAIT0(); }
        __syncthreads();

        const uint32_t* A = Asu + (c & 1) * VA_WORDS;
        const uint32_t* B = Bsu + c * 32;
        #pragma unroll
        for (int s = 0; s < 4; s++) {
            int k0 = s * 8;
            uint32_t af[4][4];
            #pragma unroll
            for (int mt = 0; mt < 4; mt++) {
                int m = mbase + mt * 16 + g;
                const uint32_t* ar  = A + (k0 + tig) * 136 + m;
                const uint32_t* ar2 = A + (k0 + tig + 4) * 136 + m;
                af[mt][0] = ar[0];  af[mt][1] = ar[8];
                af[mt][2] = ar2[0]; af[mt][3] = ar2[8];
            }
            uint32_t bf[4][2];
            #pragma unroll
            for (int nt = 0; nt < 4; nt++) {
                const uint32_t* br = B + (nbw + nt * 8 + g) * 260 + k0 + tig;
                bf[nt][0] = br[0]; bf[nt][1] = br[4];
            }
            #pragma unroll
            for (int mt = 0; mt < 4; mt++)
                #pragma unroll
                for (int nt = 0; nt < 4; nt++)
                    mma_tf32_16x8x8(acc[mt][nt], af[mt], bf[nt]);
        }
        __syncthreads();

        if (c < 6) {
            int cn = c + 2;
            #pragma unroll
            for (int i = 0; i < 4; i++) {
                int f4 = tid + 256 * i;
                int kl = f4 >> 5;
                int p4 = f4 & 31;
                const float* src = fb + (long)(cn * 32 + kl) * HW + pix0 + p4 * 4;
                uint32_t dst = as_base + (uint32_t)(((c & 1) * VA_WORDS + kl * 136 + p4 * 4) * 4);
                CP_ASYNC16(dst, src);
            }
            CP_COMMIT();
        }
    }

    float* ob = outp + (long)bz * HW * ldo;
    #pragma unroll
    for (int nt = 0; nt < 4; nt++) {
        int nc = n0 + nbw + nt * 8 + tig * 2;
        float b0 = bias[nc], b1 = bias[nc + 1];
        #pragma unroll
        for (int mt = 0; mt < 4; mt++) {
            long r = pix0 + mbase + mt * 16 + g;
            float2 v0 = make_float2(acc[mt][nt][0] + b0, acc[mt][nt][1] + b1);
            float2 v1 = make_float2(acc[mt][nt][2] + b0, acc[mt][nt][3] + b1);
            *(float2*)(ob + r * ldo + nc)       = v0;
            *(float2*)(ob + (r + 8) * ldo + nc) = v1;
        }
    }
}

// =====================================================================
// gemm_mma_a: A row-major [M][lda], W row-major [Nc][K], Out [M][ldo].
//   CTA tile 128x128, K chunks of 32, both operands double-buffered.
// =====================================================================

#define GA_WORDS (128*36)   // per buffer: 4608 words

__global__ __launch_bounds__(256, 1)
void gemm_mma_a(const float* __restrict__ A, const float* __restrict__ W,
                const float* __restrict__ bias, float* __restrict__ Out,
                int Nc, int K, int lda, int ldo, int relu)
{
    extern __shared__ float sm[];
    float* As = sm;                 // [2][128][36]
    float* Bs = sm + 2 * GA_WORDS;  // [2][128][36]

    int tid = threadIdx.x, lane = tid & 31, wid = tid >> 5;
    int g = lane >> 2, tig = lane & 3;
    int wm = wid >> 2, wn = wid & 3;
    int m0 = blockIdx.x * 128, n0 = blockIdx.y * 128;
    int nch = K >> 5;
    uint32_t asb = (uint32_t)__cvta_generic_to_shared(As);
    uint32_t bsb = (uint32_t)__cvta_generic_to_shared(Bs);

    auto load_chunk = [&](int c, int buf) {
        #pragma unroll
        for (int i = 0; i < 4; i++) {
            int f4 = tid + 256 * i;
            int r = f4 >> 3, q = f4 & 7;
            const float* srcA = A + (long)(m0 + r) * lda + c * 32 + q * 4;
            uint32_t da = asb + (uint32_t)((buf * GA_WORDS + r * 36 + q * 4) * 4);
            CP_ASYNC16(da, srcA);
            int nrow = n0 + r;
            int ok = (nrow < Nc) ? 16 : 0;
            const float* srcB = W + (long)(ok ? nrow : 0) * K + c * 32 + q * 4;
            uint32_t db = bsb + (uint32_t)((buf * GA_WORDS + r * 36 + q * 4) * 4);
            CP_ASYNC16Z(db, srcB, ok);
        }
        CP_COMMIT();
    };

    load_chunk(0, 0);
    if (nch > 1) load_chunk(1, 1);

    float acc[4][4][4];
    #pragma unroll
    for (int mt = 0; mt < 4; mt++)
        #pragma unroll
        for (int nt = 0; nt < 4; nt++)
            #pragma unroll
            for (int q = 0; q < 4; q++) acc[mt][nt][q] = 0.f;

    int mbase = wm * 64, nbw = wn * 32;

    #pragma unroll 1
    for (int c = 0; c < nch; c++) {
        if (c < nch - 2) { CP_WAIT1(); } else { CP_WAIT0(); }
        __syncthreads();

        const uint32_t* Ab = (const uint32_t*)(As + (c & 1) * GA_WORDS);
        const uint32_t* Bb = (const uint32_t*)(Bs + (c & 1) * GA_WORDS);
        #pragma unroll
        for (int s = 0; s < 4; s++) {
            int k = s * 8 + tig;
            uint32_t af[4][4];
            #pragma unroll
            for (int mt = 0; mt < 4; mt++) {
                const uint32_t* p = Ab + (mbase + mt * 16 + g) * 36 + k;
                af[mt][0] = p[0];       af[mt][1] = p[8 * 36];
                af[mt][2] = p[4];       af[mt][3] = p[8 * 36 + 4];
            }
            uint32_t bf[4][2];
            #pragma unroll
            for (int nt = 0; nt < 4; nt++) {
                const uint32_t* p = Bb + (nbw + nt * 8 + g) * 36 + k;
                bf[nt][0] = p[0]; bf[nt][1] = p[4];
            }
            #pragma unroll
            for (int mt = 0; mt < 4; mt++)
                #pragma unroll
                for (int nt = 0; nt < 4; nt++)
                    mma_tf32_16x8x8(acc[mt][nt], af[mt], bf[nt]);
        }
        __syncthreads();
        if (c + 2 < nch) load_chunk(c + 2, c & 1);
    }

    #pragma unroll
    for (int nt = 0; nt < 4; nt++) {
        int nc = n0 + nbw + nt * 8 + tig * 2;
        if (nc < Nc) {
            float b0 = bias[nc], b1 = bias[nc + 1];
            #pragma unroll
            for (int mt = 0; mt < 4; mt++) {
                long r = m0 + mbase + mt * 16 + g;
                float v0 = acc[mt][nt][0] + b0, v1 = acc[mt][nt][1] + b1;
                float v2 = acc[mt][nt][2] + b0, v3 = acc[mt][nt][3] + b1;
                if (relu) {
                    v0 = fmaxf(v0, 0.f); v1 = fmaxf(v1, 0.f);
                    v2 = fmaxf(v2, 0.f); v3 = fmaxf(v3, 0.f);
                }
                *(float2*)(Out + r * ldo + nc)       = make_float2(v0, v1);
                *(float2*)(Out + (r + 8) * ldo + nc) = make_float2(v2, v3);
            }
        }
    }
}

// =====================================================================
// scores_mma: per (b,h): S[128,128] tile = Q[128,32] @ K[128,32]^T * scale
// =====================================================================
__global__ __launch_bounds__(256, 1)
void scores_mma(const float* __restrict__ qkv, float* __restrict__ scores)
{
    __shared__ float Qs[128][36];
    __shared__ float Ks[128][36];
    int z = blockIdx.z, b = z >> 3, h = z & 7;
    int i0 = blockIdx.x * 128, j0 = blockIdx.y * 128;
    int tid = threadIdx.x, lane = tid & 31, wid = tid >> 5;
    int g = lane >> 2, tig = lane & 3;
    int wm = wid >> 2, wn = wid & 3;

    uint32_t qb = (uint32_t)__cvta_generic_to_shared(Qs);
    uint32_t kb = (uint32_t)__cvta_generic_to_shared(Ks);
    #pragma unroll
    for (int i = 0; i < 4; i++) {
        int f4 = tid + 256 * i;
        int r = f4 >> 3, q = f4 & 7;
        const float* sq = qkv + (long)(b * Nq + i0 + r) * 768 + h * 32 + q * 4;
        const float* sk = qkv + (long)(b * Nq + j0 + r) * 768 + 256 + h * 32 + q * 4;
        CP_ASYNC16(qb + (uint32_t)((r * 36 + q * 4) * 4), sq);
        CP_ASYNC16(kb + (uint32_t)((r * 36 + q * 4) * 4), sk);
    }
    CP_COMMIT();
    CP_WAIT0();
    __syncthreads();

    float acc[4][4][4];
    #pragma unroll
    for (int mt = 0; mt < 4; mt++)
        #pragma unroll
        for (int nt = 0; nt < 4; nt++)
            #pragma unroll
            for (int q = 0; q < 4; q++) acc[mt][nt][q] = 0.f;

    int mbase = wm * 64, nbw = wn * 32;
    const uint32_t* Qu = (const uint32_t*)Qs;
    const uint32_t* Ku = (const uint32_t*)Ks;
    #pragma unroll
    for (int s = 0; s < 4; s++) {
        int k = s * 8 + tig;
        uint32_t af[4][4];
        #pragma unroll
        for (int mt = 0; mt < 4; mt++) {
            const uint32_t* p = Qu + (mbase + mt * 16 + g) * 36 + k;
            af[mt][0] = p[0];  af[mt][1] = p[8 * 36];
            af[mt][2] = p[4];  af[mt][3] = p[8 * 36 + 4];
        }
        uint32_t bf[4][2];
        #pragma unroll
        for (int nt = 0; nt < 4; nt++) {
            const uint32_t* p = Ku + (nbw + nt * 8 + g) * 36 + k;
            bf[nt][0] = p[0]; bf[nt][1] = p[4];
        }
        #pragma unroll
        for (int mt = 0; mt < 4; mt++)
            #pragma unroll
            for (int nt = 0; nt < 4; nt++)
                mma_tf32_16x8x8(acc[mt][nt], af[mt], bf[nt]);
    }

    const float sc = 0.17677669529663689f;
    #pragma unroll
    for (int nt = 0; nt < 4; nt++) {
        int col = j0 + nbw + nt * 8 + tig * 2;
        #pragma unroll
        for (int mt = 0; mt < 4; mt++) {
            long r = (long)z * Nq + i0 + mbase + mt * 16 + g;
            *(float2*)(scores + r * Nq + col) =
                make_float2(acc[mt][nt][0] * sc, acc[mt][nt][1] * sc);
            *(float2*)(scores + (r + 8) * Nq + col) =
                make_float2(acc[mt][nt][2] * sc, acc[mt][nt][3] * sc);
        }
    }
}

// =====================================================================
// pv_mma: per (b,h): O[128,32] = P[128,1024] @ V[1024,32]
// =====================================================================
__global__ __launch_bounds__(256, 1)
void pv_mma(const float* __restrict__ scores, const float* __restrict__ qkv,
            float* __restrict__ sa)
{
    __shared__ float Ps[2][128][36];   // 36864 B
    __shared__ float Vs[2][32][40];    // 10240 B
    int z = blockIdx.y, b = z >> 3, h = z & 7;
    int i0 = blockIdx.x * 128;
    int tid = threadIdx.x, lane = tid & 31, wid = tid >> 5;
    int g = lane >> 2, tig = lane & 3;
    int mbase = wid * 16;

    const float* Pb = scores + ((long)z * Nq + i0) * Nq;
    const float* Vb = qkv + (long)b * Nq * 768 + 512 + h * 32;
    uint32_t pb = (uint32_t)__cvta_generic_to_shared(Ps);
    uint32_t vb = (uint32_t)__cvta_generic_to_shared(Vs);

    auto load_chunk = [&](int c, int buf) {
        #pragma unroll
        for (int i = 0; i < 4; i++) {
            int f4 = tid + 256 * i;
            int r = f4 >> 3, q = f4 & 7;
            const float* src = Pb + (long)r * Nq + c * 32 + q * 4;
            CP_ASYNC16(pb + (uint32_t)((buf * 128 * 36 + r * 36 + q * 4) * 4), src);
        }
        {
            int r = tid >> 3, q = tid & 7;
            const float* src = Vb + (long)(c * 32 + r) * 768 + q * 4;
            CP_ASYNC16(vb + (uint32_t)((buf * 32 * 40 + r * 40 + q * 4) * 4), src);
        }
        CP_COMMIT();
    };

    load_chunk(0, 0);
    load_chunk(1, 1);

    float acc[4][4];
    #pragma unroll
    for (int nt = 0; nt < 4; nt++)
        #pragma unroll
        for (int q = 0; q < 4; q++) acc[nt][q] = 0.f;

    #pragma unroll 1
    for (int c = 0; c < 32; c++) {
        if (c < 30) { CP_WAIT1(); } else { CP_WAIT0(); }
        __syncthreads();
        const uint32_t* Pu = (const uint32_t*)Ps[c & 1];
        const uint32_t* Vu = (const uint32_t*)Vs[c & 1];
        #pragma unroll
        for (int s = 0; s < 4; s++) {
            int k = s * 8 + tig;
            uint32_t af[4];
            const uint32_t* p = Pu + (mbase + g) * 36 + k;
            af[0] = p[0];       af[1] = p[8 * 36];
            af[2] = p[4];       af[3] = p[8 * 36 + 4];
            #pragma unroll
            for (int nt = 0; nt < 4; nt++) {
                uint32_t bf[2];
                const uint32_t* vp = Vu + k * 40 + nt * 8 + g;
                bf[0] = vp[0]; bf[1] = vp[4 * 40];
                mma_tf32_16x8x8(acc[nt], af, bf);
            }
        }
        __syncthreads();
        if (c + 2 < 32) load_chunk(c + 2, c & 1);
    }

    #pragma unroll
    for (int nt = 0; nt < 4; nt++) {
        int col = h * 32 + nt * 8 + tig * 2;
        long r = (long)b * Nq + i0 + mbase + g;
        *(float2*)(sa + r * 256 + col)       = make_float2(acc[nt][0], acc[nt][1]);
        *(float2*)(sa + (r + 8) * 256 + col) = make_float2(acc[nt][2], acc[nt][3]);
    }
}

// ---------------- softmax ----------------
__global__ void softmax_kernel(float* __restrict__ scores)
{
    long row = blockIdx.x;
    float* p = scores + row * Nq;
    int tid = threadIdx.x;
    float v[4];
    float mx = -1e30f;
    #pragma unroll
    for (int t=0;t<4;t++) { v[t] = p[tid + t*256]; mx = fmaxf(mx, v[t]); }
    __shared__ float sm[8];
    #pragma unroll
    for (int o=16;o>0;o>>=1) mx = fmaxf(mx, __shfl_xor_sync(0xffffffffu, mx, o));
    if ((tid & 31) == 0) sm[tid>>5] = mx;
    __syncthreads();
    float m2 = sm[0];
    #pragma unroll
    for (int w=1;w<8;w++) m2 = fmaxf(m2, sm[w]);
    float s = 0.f;
    #pragma unroll
    for (int t=0;t<4;t++) { v[t] = __expf(v[t]-m2); s += v[t]; }
    #pragma unroll
    for (int o=16;o>0;o>>=1) s += __shfl_xor_sync(0xffffffffu, s, o);
    __syncthreads();
    if ((tid & 31) == 0) sm[tid>>5] = s;
    __syncthreads();
    float st = 0.f;
    #pragma unroll
    for (int w=0;w<8;w++) st += sm[w];
    float inv = 1.f/st;
    #pragma unroll
    for (int t=0;t<4;t++) p[tid + t*256] = v[t]*inv;
}

// ---------------- residual + LayerNorm (optional transposed in/out) ----------------
__global__ void add_ln_kernel(const float* __restrict__ x, int x_t,
                              const float* __restrict__ y,
                              const float* __restrict__ g, const float* __restrict__ be,
                              float* __restrict__ out, int out_t)
{
    int bn = blockIdx.x, b = bn >> 10, n = bn & 1023;
    int c = threadIdx.x;
    float xv = x_t ? x[(long)(b*256 + c)*Nq + n] : x[(long)bn*256 + c];
    float v = xv + y[(long)bn*256 + c];
    __shared__ float s1[8], s2[8];
    float a = v, q = v*v;
    #pragma unroll
    for (int o=16;o>0;o>>=1) { a += __shfl_xor_sync(0xffffffffu, a, o); q += __shfl_xor_sync(0xffffffffu, q, o); }
    if ((c & 31) == 0) { s1[c>>5] = a; s2[c>>5] = q; }
    __syncthreads();
    float sa_ = 0.f, sq = 0.f;
    #pragma unroll
    for (int w=0;w<8;w++) { sa_ += s1[w]; sq += s2[w]; }
    float mean = sa_*(1.f/256.f);
    float var  = sq*(1.f/256.f) - mean*mean;
    float inv  = rsqrtf(var + 1e-5f);
    float o = (v - mean)*inv*g[c] + be[c];
    if (out_t) out[(long)(b*256 + c)*Nq + n] = o;
    else       out[(long)bn*256 + c] = o;
}

// ---------------- multi-scale deformable sampling ----------------
__global__ void deform_kernel(const float* __restrict__ off, const float* __restrict__ awr,
                              const float* __restrict__ qpos, float* __restrict__ ca)
{
    int bn = blockIdx.x, b = bn >> 10;
    int tid = threadIdx.x;       // tid = h*32 + d
    int h = tid >> 5;
    __shared__ float s_off[192], s_aw[96];
    if (tid < 192) s_off[tid] = off[(long)bn*192 + tid];
    if (tid < 96)  s_aw[tid]  = awr[(long)bn*96 + tid];
    __syncthreads();

    float wl[12];
    {
        float mx = -1e30f;
        #pragma unroll
        for (int t=0;t<12;t++) mx = fmaxf(mx, s_aw[h*12+t]);
        float s = 0.f;
        #pragma unroll
        for (int t=0;t<12;t++) { wl[t] = __expf(s_aw[h*12+t]-mx); s += wl[t]; }
        float inv = 1.f/s;
        #pragma unroll
        for (int t=0;t<12;t++) wl[t] *= inv;
    }
    float rx = qpos[(long)bn*2+0] * (1.f/352.f);
    float ry = qpos[(long)bn*2+1] * (1.f/400.f);
    float acc = 0.f;
    #pragma unroll
    for (int l = 0; l < 3; l++) {
        const int Hh = (l < 2) ? 200 : 400;
        const int Ww = (l < 2) ? 176 : 352;
        const long base = ((l == 0) ? VOFF0 : (l == 1) ? VOFF1 : VOFF2)
                          + (long)b * Hh * Ww * 256 + tid;
        float fx = rx * (float)Ww, fy = ry * (float)Hh;
        #pragma unroll
        for (int p = 0; p < 4; p++) {
            int oi = (h*12 + l*4 + p)*2;
            float x = fx + s_off[oi]   - 0.5f;
            float y = fy + s_off[oi+1] - 0.5f;
            float x0f = floorf(x), y0f = floorf(y);
            float wx = x - x0f, wy = y - y0f;
            float aw = wl[l*4+p];
            float w00 = (1.f-wx)*(1.f-wy)*aw, w10 = wx*(1.f-wy)*aw;
            float w01 = (1.f-wx)*wy*aw,       w11 = wx*wy*aw;
            bool vx0 = (x0f >= 0.f)  & (x0f <  (float)Ww);
            bool vx1 = (x0f >= -1.f) & (x0f <  (float)(Ww-1));
            bool vy0 = (y0f >= 0.f)  & (y0f <  (float)Hh);
            bool vy1 = (y0f >= -1.f) & (y0f <  (float)(Hh-1));
            if (vx0 | vx1) {
                int ix0 = (int)x0f;
                if (vy0 | vy1) {
                    int iy0 = (int)y0f;
                    if (vx0 && vy0) acc += w00 * g_values[base + (long)(iy0*Ww + ix0)*256];
                    if (vx1 && vy0) acc += w10 * g_values[base + (long)(iy0*Ww + ix0 + 1)*256];
                    if (vx0 && vy1) acc += w01 * g_values[base + (long)((iy0+1)*Ww + ix0)*256];
                    if (vx1 && vy1) acc += w11 * g_values[base + (long)((iy0+1)*Ww + ix0 + 1)*256];
                }
            }
        }
    }
    ca[(long)bn*256 + tid] = acc;
}

// ---------------- launch ----------------
extern "C" void kernel_launch(void* const* d_in, const int* in_sizes, int n_in,
                              void* d_out, int out_size)
{
    const float* query = (const float*)d_in[0];
    const float* qpos  = (const float*)d_in[1];
    const float* bev   = (const float*)d_in[2];
    const float* xc4   = (const float*)d_in[3];
    const float* xc3   = (const float*)d_in[4];
    const float* in_w  = (const float*)d_in[5];
    const float* in_b  = (const float*)d_in[6];
    const float* op_w  = (const float*)d_in[7];
    const float* op_b  = (const float*)d_in[8];
    const float* w_off = (const float*)d_in[9];
    const float* b_off = (const float*)d_in[10];
    const float* w_att = (const float*)d_in[11];
    const float* b_att = (const float*)d_in[12];
    const float* w_val = (const float*)d_in[13];
    const float* b_val = (const float*)d_in[14];
    const float* w_out = (const float*)d_in[15];
    const float* b_out = (const float*)d_in[16];
    const float* w_f1  = (const float*)d_in[17];
    const float* b_f1  = (const float*)d_in[18];
    const float* w_f2  = (const float*)d_in[19];
    const float* b_f2  = (const float*)d_in[20];
    const float* g1  = (const float*)d_in[21];
    const float* be1 = (const float*)d_in[22];
    const float* g2  = (const float*)d_in[23];
    const float* be2 = (const float*)d_in[24];
    const float* g3  = (const float*)d_in[25];
    const float* be3 = (const float*)d_in[26];
    float* out = (float*)d_out;
    (void)in_sizes; (void)n_in; (void)out_size;

    float *p_qkv, *p_scores, *p_sa, *p_tmp, *p_q1, *p_q2, *p_off, *p_aw, *p_ca, *p_val, *p_ffh;
    cudaGetSymbolAddress((void**)&p_qkv,    g_qkv);
    cudaGetSymbolAddress((void**)&p_scores, g_scores);
    cudaGetSymbolAddress((void**)&p_sa,     g_sa);
    cudaGetSymbolAddress((void**)&p_tmp,    g_tmp);
    cudaGetSymbolAddress((void**)&p_q1,     g_q1);
    cudaGetSymbolAddress((void**)&p_q2,     g_q2);
    cudaGetSymbolAddress((void**)&p_off,    g_off);
    cudaGetSymbolAddress((void**)&p_aw,     g_aw);
    cudaGetSymbolAddress((void**)&p_ca,     g_ca);
    cudaGetSymbolAddress((void**)&p_val,    g_values);
    cudaGetSymbolAddress((void**)&p_ffh,    g_ffh);

    cudaFuncSetAttribute(gemm_mma_at, cudaFuncAttributeMaxDynamicSharedMemorySize, VG_SMEM_B);
    cudaFuncSetAttribute(gemm_mma_a,  cudaFuncAttributeMaxDynamicSharedMemorySize, 4*GA_WORDS*4);

    // ---- value projections (tf32 mma) ----
    gemm_mma_at<<<dim3(HW0/128, 2, 2), 256, VG_SMEM_B>>>(bev, w_val, b_val, p_val + VOFF0, HW0, 256);
    gemm_mma_at<<<dim3(HW0/128, 2, 2), 256, VG_SMEM_B>>>(xc4, w_val, b_val, p_val + VOFF1, HW0, 256);
    gemm_mma_at<<<dim3(HW2/128, 2, 2), 256, VG_SMEM_B>>>(xc3, w_val, b_val, p_val + VOFF2, HW2, 256);

    // ---- self-attention ----
    gemm_mma_at<<<dim3(8, 6, 2), 256, VG_SMEM_B>>>(query, in_w, in_b, p_qkv, 1024, 768);
    scores_mma<<<dim3(8, 8, 16), 256>>>(p_qkv, p_scores);
    softmax_kernel<<<16384, 256>>>(p_scores);
    pv_mma<<<dim3(8, 16), 256>>>(p_scores, p_qkv, p_sa);
    gemm_mma_a<<<dim3(16, 2), 256, 4*GA_WORDS*4>>>(p_sa, op_w, op_b, p_tmp, 256, 256, 256, 256, 0);
    add_ln_kernel<<<2048, 256>>>(query, 1, p_tmp, g1, be1, p_q1, 0);

    // ---- deformable cross-attention ----
    gemm_mma_a<<<dim3(16, 2), 256, 4*GA_WORDS*4>>>(p_q1, w_off, b_off, p_off, 192, 256, 256, 192, 0);
    gemm_mma_a<<<dim3(16, 1), 256, 4*GA_WORDS*4>>>(p_q1, w_att, b_att, p_aw, 96, 256, 256, 96, 0);
    deform_kernel<<<2048, 256>>>(p_off, p_aw, qpos, p_ca);
    gemm_mma_a<<<dim3(16, 2), 256, 4*GA_WORDS*4>>>(p_ca, w_out, b_out, p_tmp, 256, 256, 256, 256, 0);
    add_ln_kernel<<<2048, 256>>>(p_q1, 0, p_tmp, g2, be2, p_q2, 0);

    // ---- FFN ----
    gemm_mma_a<<<dim3(16, 16), 256, 4*GA_WORDS*4>>>(p_q2, w_f1, b_f1, p_ffh, 2048, 256, 256, 2048, 1);
    gemm_mma_a<<<dim3(16, 2), 256, 4*GA_WORDS*4>>>(p_ffh, w_f2, b_f2, p_tmp, 256, 2048, 2048, 256, 0);
    add_ln_kernel<<<2048, 256>>>(p_q2, 0, p_tmp, g3, be3, out, 1);
}

// round 9
// speedup vs baseline: 6.9094x; 1.1948x over previous
#include <cuda_runtime.h>
#include <stdint.h>
#include <math.h>

// Problem constants
#define Bq 2
#define Nq 1024
#define Cc 256
#define NH 8
#define DH 32
#define FF 2048
#define HW0 35200   // 200x176
#define HW2 140800  // 400x352

// value buffer offsets (in floats), layout per level: [B, HW, 256]
#define VOFF0 0L
#define VOFF1 (2L*35200*256)
#define VOFF2 (2L*(35200+35200)*256)
#define VTOT  (2L*(35200+35200+140800)*256)

// ---------------- scratch (static device globals; no allocation) ----------------
__device__ float g_qkv[Bq*Nq*3*Cc];
__device__ float g_scores[(long)Bq*NH*Nq*Nq];   // 64 MB
__device__ float g_sa[Bq*Nq*Cc];
__device__ float g_tmp[Bq*Nq*Cc];
__device__ float g_q1[Bq*Nq*Cc];
__device__ float g_q2[Bq*Nq*Cc];
__device__ float g_off[Bq*Nq*192];
__device__ float g_aw[Bq*Nq*96];
__device__ float g_ca[Bq*Nq*Cc];
__device__ float g_ffh[Bq*Nq*FF];
__device__ float g_values[VTOT];                // 432 MB

__device__ __forceinline__ void mma_tf32_16x8x8(float* c, const uint32_t* a, const uint32_t* b) {
    asm volatile(
        "mma.sync.aligned.m16n8k8.row.col.f32.tf32.tf32.f32 "
        "{%0,%1,%2,%3}, {%4,%5,%6,%7}, {%8,%9}, {%0,%1,%2,%3};"
        : "+f"(c[0]), "+f"(c[1]), "+f"(c[2]), "+f"(c[3])
        : "r"(a[0]), "r"(a[1]), "r"(a[2]), "r"(a[3]), "r"(b[0]), "r"(b[1]));
}

#define CP_ASYNC16(dst, src) \
    asm volatile("cp.async.cg.shared.global [%0], [%1], 16;" :: "r"(dst), "l"(src) : "memory")
#define CP_ASYNC16Z(dst, src, sz) \
    asm volatile("cp.async.cg.shared.global [%0], [%1], 16, %2;" :: "r"(dst), "l"(src), "r"(sz) : "memory")
#define CP_COMMIT() asm volatile("cp.async.commit_group;" ::: "memory")
#define CP_WAIT1()  asm volatile("cp.async.wait_group 1;" ::: "memory")
#define CP_WAIT0()  asm volatile("cp.async.wait_group 0;" ::: "memory")

// =====================================================================
// gemm_mma_at: A K-major [K=256][M] (k-stride = HW), W [N,256] row-major.
//   Out[bz*HW*ldo + m*ldo + n] = sum_k A[bz*256*HW + k*HW + m] * W[n*256+k] + bias[n]
//   CTA tile 128m x 128n; BOTH operands double-buffered in 32-k chunks
//   (71.7 KB smem, <=128 regs -> 2 CTAs/SM).
// =====================================================================

#define AT_A_WORDS (32*136)    // 4352
#define AT_B_WORDS (128*36)    // 4608
#define AT_SMEM    ((2*AT_A_WORDS + 2*AT_B_WORDS) * 4)   // 71680 bytes

__global__ __launch_bounds__(256, 2)
void gemm_mma_at(const float* __restrict__ feat, const float* __restrict__ W,
                 const float* __restrict__ bias, float* __restrict__ outp,
                 int HW, int ldo)
{
    extern __shared__ float sm[];
    float* As = sm;                    // [2][32][136]
    float* Bs = sm + 2 * AT_A_WORDS;   // [2][128][36]

    int tid  = threadIdx.x;
    int lane = tid & 31, wid = tid >> 5;
    int g = lane >> 2, tig = lane & 3;
    int wm = wid >> 2, wn = wid & 3;
    long pix0 = (long)blockIdx.x * 128;
    int  n0   = blockIdx.y * 128;
    int  bz   = blockIdx.z;

    const float* fb = feat + (long)bz * 256 * HW;
    uint32_t asb = (uint32_t)__cvta_generic_to_shared(As);
    uint32_t bsb = (uint32_t)__cvta_generic_to_shared(Bs);

    auto load_chunk = [&](int c, int buf) {
        #pragma unroll
        for (int i = 0; i < 4; i++) {
            int f4 = tid + 256 * i;
            int kl = f4 >> 5, p4 = f4 & 31;
            const float* src = fb + (long)(c * 32 + kl) * HW + pix0 + p4 * 4;
            CP_ASYNC16(asb + (uint32_t)((buf * AT_A_WORDS + kl * 136 + p4 * 4) * 4), src);
        }
        #pragma unroll
        for (int i = 0; i < 4; i++) {
            int f4 = tid + 256 * i;
            int r = f4 >> 3, q = f4 & 7;
            const float* src = W + (long)(n0 + r) * 256 + c * 32 + q * 4;
            CP_ASYNC16(bsb + (uint32_t)((buf * AT_B_WORDS + r * 36 + q * 4) * 4), src);
        }
        CP_COMMIT();
    };

    load_chunk(0, 0);
    load_chunk(1, 1);

    float acc[4][4][4];
    #pragma unroll
    for (int mt = 0; mt < 4; mt++)
        #pragma unroll
        for (int nt = 0; nt < 4; nt++)
            #pragma unroll
            for (int q = 0; q < 4; q++) acc[mt][nt][q] = 0.f;

    int mbase = wm * 64, nbw = wn * 32;

    #pragma unroll 1
    for (int c = 0; c < 8; c++) {
        if (c < 6) { CP_WAIT1(); } else { CP_WAIT0(); }
        __syncthreads();

        const uint32_t* A = (const uint32_t*)(As + (c & 1) * AT_A_WORDS);
        const uint32_t* B = (const uint32_t*)(Bs + (c & 1) * AT_B_WORDS);
        #pragma unroll
        for (int s = 0; s < 4; s++) {
            int k0 = s * 8;
            uint32_t af[4][4];
            #pragma unroll
            for (int mt = 0; mt < 4; mt++) {
                int m = mbase + mt * 16 + g;
                const uint32_t* ar  = A + (k0 + tig) * 136 + m;
                const uint32_t* ar2 = A + (k0 + tig + 4) * 136 + m;
                af[mt][0] = ar[0];  af[mt][1] = ar[8];
                af[mt][2] = ar2[0]; af[mt][3] = ar2[8];
            }
            uint32_t bf[4][2];
            #pragma unroll
            for (int nt = 0; nt < 4; nt++) {
                const uint32_t* br = B + (nbw + nt * 8 + g) * 36 + k0 + tig;
                bf[nt][0] = br[0]; bf[nt][1] = br[4];
            }
            #pragma unroll
            for (int mt = 0; mt < 4; mt++)
                #pragma unroll
                for (int nt = 0; nt < 4; nt++)
                    mma_tf32_16x8x8(acc[mt][nt], af[mt], bf[nt]);
        }
        __syncthreads();
        if (c + 2 < 8) load_chunk(c + 2, c & 1);
    }

    float* ob = outp + (long)bz * HW * ldo;
    #pragma unroll
    for (int nt = 0; nt < 4; nt++) {
        int nc = n0 + nbw + nt * 8 + tig * 2;
        float b0 = bias[nc], b1 = bias[nc + 1];
        #pragma unroll
        for (int mt = 0; mt < 4; mt++) {
            long r = pix0 + mbase + mt * 16 + g;
            float2 v0 = make_float2(acc[mt][nt][0] + b0, acc[mt][nt][1] + b1);
            float2 v1 = make_float2(acc[mt][nt][2] + b0, acc[mt][nt][3] + b1);
            *(float2*)(ob + r * ldo + nc)       = v0;
            *(float2*)(ob + (r + 8) * ldo + nc) = v1;
        }
    }
}

// =====================================================================
// gemm_mma_a: A row-major [M][lda], W row-major [Nc][K], Out [M][ldo].
//   CTA tile 128x128, K chunks of 32, both operands double-buffered.
// =====================================================================

#define GA_WORDS (128*36)   // per buffer: 4608 words

__global__ __launch_bounds__(256, 2)
void gemm_mma_a(const float* __restrict__ A, const float* __restrict__ W,
                const float* __restrict__ bias, float* __restrict__ Out,
                int Nc, int K, int lda, int ldo, int relu)
{
    extern __shared__ float sm[];
    float* As = sm;                 // [2][128][36]
    float* Bs = sm + 2 * GA_WORDS;  // [2][128][36]

    int tid = threadIdx.x, lane = tid & 31, wid = tid >> 5;
    int g = lane >> 2, tig = lane & 3;
    int wm = wid >> 2, wn = wid & 3;
    int m0 = blockIdx.x * 128, n0 = blockIdx.y * 128;
    int nch = K >> 5;
    uint32_t asb = (uint32_t)__cvta_generic_to_shared(As);
    uint32_t bsb = (uint32_t)__cvta_generic_to_shared(Bs);

    auto load_chunk = [&](int c, int buf) {
        #pragma unroll
        for (int i = 0; i < 4; i++) {
            int f4 = tid + 256 * i;
            int r = f4 >> 3, q = f4 & 7;
            const float* srcA = A + (long)(m0 + r) * lda + c * 32 + q * 4;
            uint32_t da = asb + (uint32_t)((buf * GA_WORDS + r * 36 + q * 4) * 4);
            CP_ASYNC16(da, srcA);
            int nrow = n0 + r;
            int ok = (nrow < Nc) ? 16 : 0;
            const float* srcB = W + (long)(ok ? nrow : 0) * K + c * 32 + q * 4;
            uint32_t db = bsb + (uint32_t)((buf * GA_WORDS + r * 36 + q * 4) * 4);
            CP_ASYNC16Z(db, srcB, ok);
        }
        CP_COMMIT();
    };

    load_chunk(0, 0);
    if (nch > 1) load_chunk(1, 1);

    float acc[4][4][4];
    #pragma unroll
    for (int mt = 0; mt < 4; mt++)
        #pragma unroll
        for (int nt = 0; nt < 4; nt++)
            #pragma unroll
            for (int q = 0; q < 4; q++) acc[mt][nt][q] = 0.f;

    int mbase = wm * 64, nbw = wn * 32;

    #pragma unroll 1
    for (int c = 0; c < nch; c++) {
        if (c < nch - 2) { CP_WAIT1(); } else { CP_WAIT0(); }
        __syncthreads();

        const uint32_t* Ab = (const uint32_t*)(As + (c & 1) * GA_WORDS);
        const uint32_t* Bb = (const uint32_t*)(Bs + (c & 1) * GA_WORDS);
        #pragma unroll
        for (int s = 0; s < 4; s++) {
            int k = s * 8 + tig;
            uint32_t af[4][4];
            #pragma unroll
            for (int mt = 0; mt < 4; mt++) {
                const uint32_t* p = Ab + (mbase + mt * 16 + g) * 36 + k;
                af[mt][0] = p[0];       af[mt][1] = p[8 * 36];
                af[mt][2] = p[4];       af[mt][3] = p[8 * 36 + 4];
            }
            uint32_t bf[4][2];
            #pragma unroll
            for (int nt = 0; nt < 4; nt++) {
                const uint32_t* p = Bb + (nbw + nt * 8 + g) * 36 + k;
                bf[nt][0] = p[0]; bf[nt][1] = p[4];
            }
            #pragma unroll
            for (int mt = 0; mt < 4; mt++)
                #pragma unroll
                for (int nt = 0; nt < 4; nt++)
                    mma_tf32_16x8x8(acc[mt][nt], af[mt], bf[nt]);
        }
        __syncthreads();
        if (c + 2 < nch) load_chunk(c + 2, c & 1);
    }

    #pragma unroll
    for (int nt = 0; nt < 4; nt++) {
        int nc = n0 + nbw + nt * 8 + tig * 2;
        if (nc < Nc) {
            float b0 = bias[nc], b1 = bias[nc + 1];
            #pragma unroll
            for (int mt = 0; mt < 4; mt++) {
                long r = m0 + mbase + mt * 16 + g;
                float v0 = acc[mt][nt][0] + b0, v1 = acc[mt][nt][1] + b1;
                float v2 = acc[mt][nt][2] + b0, v3 = acc[mt][nt][3] + b1;
                if (relu) {
                    v0 = fmaxf(v0, 0.f); v1 = fmaxf(v1, 0.f);
                    v2 = fmaxf(v2, 0.f); v3 = fmaxf(v3, 0.f);
                }
                *(float2*)(Out + r * ldo + nc)       = make_float2(v0, v1);
                *(float2*)(Out + (r + 8) * ldo + nc) = make_float2(v2, v3);
            }
        }
    }
}

// =====================================================================
// scores_mma: per (b,h): S[128,128] tile = Q[128,32] @ K[128,32]^T * scale
// =====================================================================
__global__ __launch_bounds__(256, 2)
void scores_mma(const float* __restrict__ qkv, float* __restrict__ scores)
{
    __shared__ float Qs[128][36];
    __shared__ float Ks[128][36];
    int z = blockIdx.z, b = z >> 3, h = z & 7;
    int i0 = blockIdx.x * 128, j0 = blockIdx.y * 128;
    int tid = threadIdx.x, lane = tid & 31, wid = tid >> 5;
    int g = lane >> 2, tig = lane & 3;
    int wm = wid >> 2, wn = wid & 3;

    uint32_t qb = (uint32_t)__cvta_generic_to_shared(Qs);
    uint32_t kb = (uint32_t)__cvta_generic_to_shared(Ks);
    #pragma unroll
    for (int i = 0; i < 4; i++) {
        int f4 = tid + 256 * i;
        int r = f4 >> 3, q = f4 & 7;
        const float* sq = qkv + (long)(b * Nq + i0 + r) * 768 + h * 32 + q * 4;
        const float* sk = qkv + (long)(b * Nq + j0 + r) * 768 + 256 + h * 32 + q * 4;
        CP_ASYNC16(qb + (uint32_t)((r * 36 + q * 4) * 4), sq);
        CP_ASYNC16(kb + (uint32_t)((r * 36 + q * 4) * 4), sk);
    }
    CP_COMMIT();
    CP_WAIT0();
    __syncthreads();

    float acc[4][4][4];
    #pragma unroll
    for (int mt = 0; mt < 4; mt++)
        #pragma unroll
        for (int nt = 0; nt < 4; nt++)
            #pragma unroll
            for (int q = 0; q < 4; q++) acc[mt][nt][q] = 0.f;

    int mbase = wm * 64, nbw = wn * 32;
    const uint32_t* Qu = (const uint32_t*)Qs;
    const uint32_t* Ku = (const uint32_t*)Ks;
    #pragma unroll
    for (int s = 0; s < 4; s++) {
        int k = s * 8 + tig;
        uint32_t af[4][4];
        #pragma unroll
        for (int mt = 0; mt < 4; mt++) {
            const uint32_t* p = Qu + (mbase + mt * 16 + g) * 36 + k;
            af[mt][0] = p[0];  af[mt][1] = p[8 * 36];
            af[mt][2] = p[4];  af[mt][3] = p[8 * 36 + 4];
        }
        uint32_t bf[4][2];
        #pragma unroll
        for (int nt = 0; nt < 4; nt++) {
            const uint32_t* p = Ku + (nbw + nt * 8 + g) * 36 + k;
            bf[nt][0] = p[0]; bf[nt][1] = p[4];
        }
        #pragma unroll
        for (int mt = 0; mt < 4; mt++)
            #pragma unroll
            for (int nt = 0; nt < 4; nt++)
                mma_tf32_16x8x8(acc[mt][nt], af[mt], bf[nt]);
    }

    const float sc = 0.17677669529663689f;
    #pragma unroll
    for (int nt = 0; nt < 4; nt++) {
        int col = j0 + nbw + nt * 8 + tig * 2;
        #pragma unroll
        for (int mt = 0; mt < 4; mt++) {
            long r = (long)z * Nq + i0 + mbase + mt * 16 + g;
            *(float2*)(scores + r * Nq + col) =
                make_float2(acc[mt][nt][0] * sc, acc[mt][nt][1] * sc);
            *(float2*)(scores + (r + 8) * Nq + col) =
                make_float2(acc[mt][nt][2] * sc, acc[mt][nt][3] * sc);
        }
    }
}

// =====================================================================
// pv_mma: per (b,h): O[128,32] = P[128,1024] @ V[1024,32]
// =====================================================================
__global__ __launch_bounds__(256, 2)
void pv_mma(const float* __restrict__ scores, const float* __restrict__ qkv,
            float* __restrict__ sa)
{
    __shared__ float Ps[2][128][36];   // 36864 B
    __shared__ float Vs[2][32][40];    // 10240 B
    int z = blockIdx.y, b = z >> 3, h = z & 7;
    int i0 = blockIdx.x * 128;
    int tid = threadIdx.x, lane = tid & 31, wid = tid >> 5;
    int g = lane >> 2, tig = lane & 3;
    int mbase = wid * 16;

    const float* Pb = scores + ((long)z * Nq + i0) * Nq;
    const float* Vb = qkv + (long)b * Nq * 768 + 512 + h * 32;
    uint32_t pb = (uint32_t)__cvta_generic_to_shared(Ps);
    uint32_t vb = (uint32_t)__cvta_generic_to_shared(Vs);

    auto load_chunk = [&](int c, int buf) {
        #pragma unroll
        for (int i = 0; i < 4; i++) {
            int f4 = tid + 256 * i;
            int r = f4 >> 3, q = f4 & 7;
            const float* src = Pb + (long)r * Nq + c * 32 + q * 4;
            CP_ASYNC16(pb + (uint32_t)((buf * 128 * 36 + r * 36 + q * 4) * 4), src);
        }
        {
            int r = tid >> 3, q = tid & 7;
            const float* src = Vb + (long)(c * 32 + r) * 768 + q * 4;
            CP_ASYNC16(vb + (uint32_t)((buf * 32 * 40 + r * 40 + q * 4) * 4), src);
        }
        CP_COMMIT();
    };

    load_chunk(0, 0);
    load_chunk(1, 1);

    float acc[4][4];
    #pragma unroll
    for (int nt = 0; nt < 4; nt++)
        #pragma unroll
        for (int q = 0; q < 4; q++) acc[nt][q] = 0.f;

    #pragma unroll 1
    for (int c = 0; c < 32; c++) {
        if (c < 30) { CP_WAIT1(); } else { CP_WAIT0(); }
        __syncthreads();
        const uint32_t* Pu = (const uint32_t*)Ps[c & 1];
        const uint32_t* Vu = (const uint32_t*)Vs[c & 1];
        #pragma unroll
        for (int s = 0; s < 4; s++) {
            int k = s * 8 + tig;
            uint32_t af[4];
            const uint32_t* p = Pu + (mbase + g) * 36 + k;
            af[0] = p[0];       af[1] = p[8 * 36];
            af[2] = p[4];       af[3] = p[8 * 36 + 4];
            #pragma unroll
            for (int nt = 0; nt < 4; nt++) {
                uint32_t bf[2];
                const uint32_t* vp = Vu + k * 40 + nt * 8 + g;
                bf[0] = vp[0]; bf[1] = vp[4 * 40];
                mma_tf32_16x8x8(acc[nt], af, bf);
            }
        }
        __syncthreads();
        if (c + 2 < 32) load_chunk(c + 2, c & 1);
    }

    #pragma unroll
    for (int nt = 0; nt < 4; nt++) {
        int col = h * 32 + nt * 8 + tig * 2;
        long r = (long)b * Nq + i0 + mbase + g;
        *(float2*)(sa + r * 256 + col)       = make_float2(acc[nt][0], acc[nt][1]);
        *(float2*)(sa + (r + 8) * 256 + col) = make_float2(acc[nt][2], acc[nt][3]);
    }
}

// ---------------- softmax ----------------
__global__ void softmax_kernel(float* __restrict__ scores)
{
    long row = blockIdx.x;
    float* p = scores + row * Nq;
    int tid = threadIdx.x;
    float v[4];
    float mx = -1e30f;
    #pragma unroll
    for (int t=0;t<4;t++) { v[t] = p[tid + t*256]; mx = fmaxf(mx, v[t]); }
    __shared__ float sm[8];
    #pragma unroll
    for (int o=16;o>0;o>>=1) mx = fmaxf(mx, __shfl_xor_sync(0xffffffffu, mx, o));
    if ((tid & 31) == 0) sm[tid>>5] = mx;
    __syncthreads();
    float m2 = sm[0];
    #pragma unroll
    for (int w=1;w<8;w++) m2 = fmaxf(m2, sm[w]);
    float s = 0.f;
    #pragma unroll
    for (int t=0;t<4;t++) { v[t] = __expf(v[t]-m2); s += v[t]; }
    #pragma unroll
    for (int o=16;o>0;o>>=1) s += __shfl_xor_sync(0xffffffffu, s, o);
    __syncthreads();
    if ((tid & 31) == 0) sm[tid>>5] = s;
    __syncthreads();
    float st = 0.f;
    #pragma unroll
    for (int w=0;w<8;w++) st += sm[w];
    float inv = 1.f/st;
    #pragma unroll
    for (int t=0;t<4;t++) p[tid + t*256] = v[t]*inv;
}

// ---------------- residual + LayerNorm (optional transposed in/out) ----------------
__global__ void add_ln_kernel(const float* __restrict__ x, int x_t,
                              const float* __restrict__ y,
                              const float* __restrict__ g, const float* __restrict__ be,
                              float* __restrict__ out, int out_t)
{
    int bn = blockIdx.x, b = bn >> 10, n = bn & 1023;
    int c = threadIdx.x;
    float xv = x_t ? x[(long)(b*256 + c)*Nq + n] : x[(long)bn*256 + c];
    float v = xv + y[(long)bn*256 + c];
    __shared__ float s1[8], s2[8];
    float a = v, q = v*v;
    #pragma unroll
    for (int o=16;o>0;o>>=1) { a += __shfl_xor_sync(0xffffffffu, a, o); q += __shfl_xor_sync(0xffffffffu, q, o); }
    if ((c & 31) == 0) { s1[c>>5] = a; s2[c>>5] = q; }
    __syncthreads();
    float sa_ = 0.f, sq = 0.f;
    #pragma unroll
    for (int w=0;w<8;w++) { sa_ += s1[w]; sq += s2[w]; }
    float mean = sa_*(1.f/256.f);
    float var  = sq*(1.f/256.f) - mean*mean;
    float inv  = rsqrtf(var + 1e-5f);
    float o = (v - mean)*inv*g[c] + be[c];
    if (out_t) out[(long)(b*256 + c)*Nq + n] = o;
    else       out[(long)bn*256 + c] = o;
}

// ---------------- multi-scale deformable sampling ----------------
__global__ void deform_kernel(const float* __restrict__ off, const float* __restrict__ awr,
                              const float* __restrict__ qpos, float* __restrict__ ca)
{
    int bn = blockIdx.x, b = bn >> 10;
    int tid = threadIdx.x;       // tid = h*32 + d
    int h = tid >> 5;
    __shared__ float s_off[192], s_aw[96];
    if (tid < 192) s_off[tid] = off[(long)bn*192 + tid];
    if (tid < 96)  s_aw[tid]  = awr[(long)bn*96 + tid];
    __syncthreads();

    float wl[12];
    {
        float mx = -1e30f;
        #pragma unroll
        for (int t=0;t<12;t++) mx = fmaxf(mx, s_aw[h*12+t]);
        float s = 0.f;
        #pragma unroll
        for (int t=0;t<12;t++) { wl[t] = __expf(s_aw[h*12+t]-mx); s += wl[t]; }
        float inv = 1.f/s;
        #pragma unroll
        for (int t=0;t<12;t++) wl[t] *= inv;
    }
    float rx = qpos[(long)bn*2+0] * (1.f/352.f);
    float ry = qpos[(long)bn*2+1] * (1.f/400.f);
    float acc = 0.f;
    #pragma unroll
    for (int l = 0; l < 3; l++) {
        const int Hh = (l < 2) ? 200 : 400;
        const int Ww = (l < 2) ? 176 : 352;
        const long base = ((l == 0) ? VOFF0 : (l == 1) ? VOFF1 : VOFF2)
                          + (long)b * Hh * Ww * 256 + tid;
        float fx = rx * (float)Ww, fy = ry * (float)Hh;
        #pragma unroll
        for (int p = 0; p < 4; p++) {
            int oi = (h*12 + l*4 + p)*2;
            float x = fx + s_off[oi]   - 0.5f;
            float y = fy + s_off[oi+1] - 0.5f;
            float x0f = floorf(x), y0f = floorf(y);
            float wx = x - x0f, wy = y - y0f;
            float aw = wl[l*4+p];
            float w00 = (1.f-wx)*(1.f-wy)*aw, w10 = wx*(1.f-wy)*aw;
            float w01 = (1.f-wx)*wy*aw,       w11 = wx*wy*aw;
            bool vx0 = (x0f >= 0.f)  & (x0f <  (float)Ww);
            bool vx1 = (x0f >= -1.f) & (x0f <  (float)(Ww-1));
            bool vy0 = (y0f >= 0.f)  & (y0f <  (float)Hh);
            bool vy1 = (y0f >= -1.f) & (y0f <  (float)(Hh-1));
            if (vx0 | vx1) {
                int ix0 = (int)x0f;
                if (vy0 | vy1) {
                    int iy0 = (int)y0f;
                    if (vx0 && vy0) acc += w00 * g_values[base + (long)(iy0*Ww + ix0)*256];
                    if (vx1 && vy0) acc += w10 * g_values[base + (long)(iy0*Ww + ix0 + 1)*256];
                    if (vx0 && vy1) acc += w01 * g_values[base + (long)((iy0+1)*Ww + ix0)*256];
                    if (vx1 && vy1) acc += w11 * g_values[base + (long)((iy0+1)*Ww + ix0 + 1)*256];
                }
            }
        }
    }
    ca[(long)bn*256 + tid] = acc;
}

// ---------------- launch ----------------
extern "C" void kernel_launch(void* const* d_in, const int* in_sizes, int n_in,
                              void* d_out, int out_size)
{
    const float* query = (const float*)d_in[0];
    const float* qpos  = (const float*)d_in[1];
    const float* bev   = (const float*)d_in[2];
    const float* xc4   = (const float*)d_in[3];
    const float* xc3   = (const float*)d_in[4];
    const float* in_w  = (const float*)d_in[5];
    const float* in_b  = (const float*)d_in[6];
    const float* op_w  = (const float*)d_in[7];
    const float* op_b  = (const float*)d_in[8];
    const float* w_off = (const float*)d_in[9];
    const float* b_off = (const float*)d_in[10];
    const float* w_att = (const float*)d_in[11];
    const float* b_att = (const float*)d_in[12];
    const float* w_val = (const float*)d_in[13];
    const float* b_val = (const float*)d_in[14];
    const float* w_out = (const float*)d_in[15];
    const float* b_out = (const float*)d_in[16];
    const float* w_f1  = (const float*)d_in[17];
    const float* b_f1  = (const float*)d_in[18];
    const float* w_f2  = (const float*)d_in[19];
    const float* b_f2  = (const float*)d_in[20];
    const float* g1  = (const float*)d_in[21];
    const float* be1 = (const float*)d_in[22];
    const float* g2  = (const float*)d_in[23];
    const float* be2 = (const float*)d_in[24];
    const float* g3  = (const float*)d_in[25];
    const float* be3 = (const float*)d_in[26];
    float* out = (float*)d_out;
    (void)in_sizes; (void)n_in; (void)out_size;

    float *p_qkv, *p_scores, *p_sa, *p_tmp, *p_q1, *p_q2, *p_off, *p_aw, *p_ca, *p_val, *p_ffh;
    cudaGetSymbolAddress((void**)&p_qkv,    g_qkv);
    cudaGetSymbolAddress((void**)&p_scores, g_scores);
    cudaGetSymbolAddress((void**)&p_sa,     g_sa);
    cudaGetSymbolAddress((void**)&p_tmp,    g_tmp);
    cudaGetSymbolAddress((void**)&p_q1,     g_q1);
    cudaGetSymbolAddress((void**)&p_q2,     g_q2);
    cudaGetSymbolAddress((void**)&p_off,    g_off);
    cudaGetSymbolAddress((void**)&p_aw,     g_aw);
    cudaGetSymbolAddress((void**)&p_ca,     g_ca);
    cudaGetSymbolAddress((void**)&p_val,    g_values);
    cudaGetSymbolAddress((void**)&p_ffh,    g_ffh);

    cudaFuncSetAttribute(gemm_mma_at, cudaFuncAttributeMaxDynamicSharedMemorySize, AT_SMEM);
    cudaFuncSetAttribute(gemm_mma_a,  cudaFuncAttributeMaxDynamicSharedMemorySize, 4*GA_WORDS*4);

    // ---- value projections (tf32 mma) ----
    gemm_mma_at<<<dim3(HW0/128, 2, 2), 256, AT_SMEM>>>(bev, w_val, b_val, p_val + VOFF0, HW0, 256);
    gemm_mma_at<<<dim3(HW0/128, 2, 2), 256, AT_SMEM>>>(xc4, w_val, b_val, p_val + VOFF1, HW0, 256);
    gemm_mma_at<<<dim3(HW2/128, 2, 2), 256, AT_SMEM>>>(xc3, w_val, b_val, p_val + VOFF2, HW2, 256);

    // ---- self-attention ----
    gemm_mma_at<<<dim3(8, 6, 2), 256, AT_SMEM>>>(query, in_w, in_b, p_qkv, 1024, 768);
    scores_mma<<<dim3(8, 8, 16), 256>>>(p_qkv, p_scores);
    softmax_kernel<<<16384, 256>>>(p_scores);
    pv_mma<<<dim3(8, 16), 256>>>(p_scores, p_qkv, p_sa);
    gemm_mma_a<<<dim3(16, 2), 256, 4*GA_WORDS*4>>>(p_sa, op_w, op_b, p_tmp, 256, 256, 256, 256, 0);
    add_ln_kernel<<<2048, 256>>>(query, 1, p_tmp, g1, be1, p_q1, 0);

    // ---- deformable cross-attention ----
    gemm_mma_a<<<dim3(16, 2), 256, 4*GA_WORDS*4>>>(p_q1, w_off, b_off, p_off, 192, 256, 256, 192, 0);
    gemm_mma_a<<<dim3(16, 1), 256, 4*GA_WORDS*4>>>(p_q1, w_att, b_att, p_aw, 96, 256, 256, 96, 0);
    deform_kernel<<<2048, 256>>>(p_off, p_aw, qpos, p_ca);
    gemm_mma_a<<<dim3(16, 2), 256, 4*GA_WORDS*4>>>(p_ca, w_out, b_out, p_tmp, 256, 256, 256, 256, 0);
    add_ln_kernel<<<2048, 256>>>(p_q1, 0, p_tmp, g2, be2, p_q2, 0);

    // ---- FFN ----
    gemm_mma_a<<<dim3(16, 16), 256, 4*GA_WORDS*4>>>(p_q2, w_f1, b_f1, p_ffh, 2048, 256, 256, 2048, 1);
    gemm_mma_a<<<dim3(16, 2), 256, 4*GA_WORDS*4>>>(p_ffh, w_f2, b_f2, p_tmp, 256, 2048, 2048, 256, 0);
    add_ln_kernel<<<2048, 256>>>(p_q2, 0, p_tmp, g3, be3, out, 1);
}